// round 1
// baseline (speedup 1.0000x reference)
#include <cuda_runtime.h>
#include <math.h>

// ---------------- scratch (static __device__, no runtime alloc) ----------------
__device__ float d_full[10 * 192 * 192];          // full-res input
__device__ float d_f0[100 * 192 * 192];           // feature ping
__device__ float d_f1[100 * 192 * 192];           // feature pong
__device__ float d_colbuf[36864 * 900];           // im2col scratch (max 33.18M)
__device__ float d_g0[1024 * 48 * 48];            // weight-net ping
__device__ float d_g1[1024 * 48 * 48];            // weight-net pong
__device__ float d_h[6272 * 48 * 48];             // half layer
__device__ float d_wm[2304 * 12544];              // Wmap, PIXEL-major [p][c]

// ---------------- f32x2 packed FMA helpers (sm_103a FFMA2) ----------------
__device__ __forceinline__ unsigned long long pk2(float lo, float hi) {
    unsigned long long r;
    asm("mov.b64 %0, {%1, %2};" : "=l"(r) : "f"(lo), "f"(hi));
    return r;
}
__device__ __forceinline__ void fma2(unsigned long long &d, unsigned long long a, unsigned long long b) {
    asm("fma.rn.f32x2 %0, %1, %2, %0;" : "+l"(d) : "l"(a), "l"(b));
}
__device__ __forceinline__ float2 up2(unsigned long long v) {
    float lo, hi;
    asm("mov.b64 {%0, %1}, %2;" : "=f"(lo), "=f"(hi) : "l"(v));
    return make_float2(lo, hi);
}

// ---------------- make_full: (16,10,48,48) tiles -> (10,192,192) ----------------
__global__ void make_full_kernel(const float* __restrict__ in, float* __restrict__ out) {
    int idx = blockIdx.x * blockDim.x + threadIdx.x;
    if (idx >= 10 * 192 * 192) return;
    int x = idx % 192;
    int y = (idx / 192) % 192;
    int c = idx / (192 * 192);
    int w = x >> 2, s2 = x & 3;
    int h = y >> 2, s1 = y & 3;
    int t = s1 * 4 + s2;
    out[idx] = in[((t * 10 + c) * 48 + h) * 48 + w];
}

// ---------------- generic im2col ----------------
// col[m][k], m = y*Wout+x, k = (c*kh+i)*kw+j
__global__ void im2col_kernel(const float* __restrict__ in, float* __restrict__ col,
                              int C, int Hin, int Win, int Hout, int Wout,
                              int kh, int kw, int stride, int pad) {
    int K = C * kh * kw;
    int total = Hout * Wout * K;
    for (int idx = blockIdx.x * blockDim.x + threadIdx.x; idx < total;
         idx += gridDim.x * blockDim.x) {
        int m = idx / K;
        int k = idx - m * K;
        int x = m % Wout, y = m / Wout;
        int j = k % kw;
        int i = (k / kw) % kh;
        int c = k / (kw * kh);
        int iy = y * stride + i - pad;
        int ix = x * stride + j - pad;
        float v = 0.f;
        if (iy >= 0 && iy < Hin && ix >= 0 && ix < Win)
            v = in[(c * Hin + iy) * Win + ix];
        col[idx] = v;
    }
}

// ---------------- fp32(x2) GEMM: C[n][m] (or C[m][n]) = sum_k A[m][k]*B[n][k] + bias[n] ----------------
// act: 0 none, 1 leaky-relu(0.01), 2 tanh.  outPM: 1 -> C row-major [M][N] (pixel-major)
#define BM 128
#define BN 128
#define BK 8
__global__ __launch_bounds__(256, 2) void gemm_kernel(
    const float* __restrict__ A, const float* __restrict__ B,
    const float* __restrict__ bias, float* __restrict__ C,
    int M, int N, int K, int act, int outPM) {
    __shared__ __align__(16) float As[2][BK][BM];
    __shared__ __align__(16) float Bs[2][BK][BN];
    const int tid = threadIdx.x;
    const int m0 = blockIdx.y * BM, n0 = blockIdx.x * BN;
    const int tm = tid >> 4, tn = tid & 15;
    const int lRow = tid >> 1;
    const int lCol = (tid & 1) * 4;
    const bool aOk = (m0 + lRow) < M;
    const bool bOk = (n0 + lRow) < N;
    const float* Ap = A + (size_t)(m0 + lRow) * K;
    const float* Bp = B + (size_t)(n0 + lRow) * K;

    unsigned long long acc2[8][4];
#pragma unroll
    for (int i = 0; i < 8; i++)
#pragma unroll
        for (int j = 0; j < 4; j++) acc2[i][j] = 0ULL;

    const int nk = (K + BK - 1) / BK;
    float ra[4], rb[4];
    // prologue: tile 0
#pragma unroll
    for (int j = 0; j < 4; j++) {
        int kk = lCol + j;
        ra[j] = (aOk && kk < K) ? Ap[kk] : 0.f;
        rb[j] = (bOk && kk < K) ? Bp[kk] : 0.f;
    }
#pragma unroll
    for (int j = 0; j < 4; j++) {
        As[0][lCol + j][lRow] = ra[j];
        Bs[0][lCol + j][lRow] = rb[j];
    }
    __syncthreads();

    for (int kt = 0; kt < nk; kt++) {
        if (kt + 1 < nk) {
            int kb = (kt + 1) * BK + lCol;
#pragma unroll
            for (int j = 0; j < 4; j++) {
                int kk = kb + j;
                ra[j] = (aOk && kk < K) ? Ap[kk] : 0.f;
                rb[j] = (bOk && kk < K) ? Bp[kk] : 0.f;
            }
        }
        const int cb = kt & 1;
#pragma unroll
        for (int k = 0; k < BK; k++) {
            float4 a0 = *(const float4*)&As[cb][k][tm * 4];
            float4 a1 = *(const float4*)&As[cb][k][64 + tm * 4];
            ulonglong2 bq0 = *(const ulonglong2*)&Bs[cb][k][tn * 4];
            ulonglong2 bq1 = *(const ulonglong2*)&Bs[cb][k][64 + tn * 4];
            unsigned long long ad[8];
            ad[0] = pk2(a0.x, a0.x); ad[1] = pk2(a0.y, a0.y);
            ad[2] = pk2(a0.z, a0.z); ad[3] = pk2(a0.w, a0.w);
            ad[4] = pk2(a1.x, a1.x); ad[5] = pk2(a1.y, a1.y);
            ad[6] = pk2(a1.z, a1.z); ad[7] = pk2(a1.w, a1.w);
            unsigned long long bd[4] = {bq0.x, bq0.y, bq1.x, bq1.y};
#pragma unroll
            for (int i = 0; i < 8; i++)
#pragma unroll
                for (int jp = 0; jp < 4; jp++)
                    fma2(acc2[i][jp], ad[i], bd[jp]);
        }
        if (kt + 1 < nk) {
            const int nb = (kt + 1) & 1;
#pragma unroll
            for (int j = 0; j < 4; j++) {
                As[nb][lCol + j][lRow] = ra[j];
                Bs[nb][lCol + j][lRow] = rb[j];
            }
        }
        __syncthreads();
    }

    // epilogue
#pragma unroll
    for (int i = 0; i < 8; i++) {
        int mg = m0 + ((i < 4) ? (tm * 4 + i) : (64 + tm * 4 + i - 4));
        if (mg >= M) continue;
#pragma unroll
        for (int jp = 0; jp < 4; jp++) {
            float2 v = up2(acc2[i][jp]);
            int ng = n0 + ((jp < 2) ? 0 : 64) + tn * 4 + (jp & 1) * 2;
#pragma unroll
            for (int h = 0; h < 2; h++) {
                int nn = ng + h;
                if (nn >= N) continue;
                float val = (h == 0 ? v.x : v.y) + bias[nn];
                if (act == 1) val = val > 0.f ? val : 0.01f * val;
                else if (act == 2) val = tanhf(val);
                if (outPM) C[(size_t)mg * N + nn] = val;
                else       C[(size_t)nn * M + mg] = val;
            }
        }
    }
}

// ---------------- per-pixel normal-equations solve ----------------
// wmap: [2304][12544] pixel-major. design: (16,7,48,48). input: (16,10,48,48).
// out: (16,3,48,48)
__global__ __launch_bounds__(256) void solve_kernel(
    const float* __restrict__ wmap, const float* __restrict__ design,
    const float* __restrict__ input, float* __restrict__ out) {
    const int p = blockIdx.x;
    const int y = p / 48, x = p % 48;
    const int tid = threadIdx.x;
    __shared__ float sWm[16][17];
    __shared__ float sM[16][17];
    __shared__ float sX[16][8];   // [t][cd], cd<7
    __shared__ float sY[16][4];   // [t][ch], ch<3
    __shared__ float sXTW[7][16];
    __shared__ float sA[49];
    __shared__ float sB[21];
    __shared__ float sPara[7][3];

    if (tid < 49) sA[tid] = 0.f;
    if (tid < 21) sB[tid] = 0.f;
    const int t1 = tid >> 4, t2 = tid & 15;
    const float* wp = wmap + (size_t)p * 12544;

    for (int ni = 0; ni < 49; ni++) {
        int ny = y + ni / 7 - 3;
        int nx = x + ni % 7 - 3;
        bool inb = ((unsigned)ny < 48u) && ((unsigned)nx < 48u);
        __syncthreads();  // previous-iter readers done before we overwrite
        // Wm[t1][t2] = Wmap channel ni*256 + t1*16 + t2 (coalesced)
        sWm[t1][t2] = wp[ni * 256 + tid];
        if (tid < 112) {
            int t = tid / 7, cd = tid - t * 7;
            sX[t][cd] = inb ? design[(t * 7 + cd) * 2304 + ny * 48 + nx] : 0.f;
        }
        if (tid >= 128 && tid < 176) {
            int r = tid - 128;
            int t = r / 3, ch = r - t * 3;
            sY[t][ch] = inb ? input[(t * 10 + ch) * 2304 + ny * 48 + nx] : 0.f;
        }
        __syncthreads();
        // M = Wm Wm^T + I
        float s = (t1 == t2) ? 1.f : 0.f;
#pragma unroll
        for (int k = 0; k < 16; k++) s += sWm[t1][k] * sWm[t2][k];
        sM[t1][t2] = s;
        __syncthreads();
        // XTW[cd][t] = sum_t1 X[t1][cd] * M[t1][t]
        if (tid < 112) {
            int cd = tid >> 4, t = tid & 15;
            float v = 0.f;
#pragma unroll
            for (int k = 0; k < 16; k++) v += sX[k][cd] * sM[k][t];
            sXTW[cd][t] = v;
        }
        __syncthreads();
        // A += XTW X ; Bv += XTW Y
        if (tid < 49) {
            int cd = tid / 7, ce = tid - cd * 7;
            float v = 0.f;
#pragma unroll
            for (int t = 0; t < 16; t++) v += sXTW[cd][t] * sX[t][ce];
            sA[tid] += v;
        }
        if (tid >= 64 && tid < 85) {
            int r = tid - 64;
            int cd = r / 3, ch = r - cd * 3;
            float v = 0.f;
#pragma unroll
            for (int t = 0; t < 16; t++) v += sXTW[cd][t] * sY[t][ch];
            sB[r] += v;
        }
    }
    __syncthreads();

    if (tid == 0) {
        float a[7][7], b[7][3];
        for (int i = 0; i < 7; i++) {
            for (int j = 0; j < 7; j++) a[i][j] = sA[i * 7 + j];
            a[i][i] += 0.01f;
            for (int c = 0; c < 3; c++) b[i][c] = sB[i * 3 + c];
        }
        // Gauss-Jordan with partial pivoting
        for (int col = 0; col < 7; col++) {
            int piv = col;
            float mx = fabsf(a[col][col]);
            for (int r = col + 1; r < 7; r++) {
                float v = fabsf(a[r][col]);
                if (v > mx) { mx = v; piv = r; }
            }
            if (piv != col) {
                for (int c = 0; c < 7; c++) { float t = a[col][c]; a[col][c] = a[piv][c]; a[piv][c] = t; }
                for (int c = 0; c < 3; c++) { float t = b[col][c]; b[col][c] = b[piv][c]; b[piv][c] = t; }
            }
            float inv = 1.f / a[col][col];
            for (int r = 0; r < 7; r++) {
                if (r == col) continue;
                float f = a[r][col] * inv;
                for (int c = col; c < 7; c++) a[r][c] -= f * a[col][c];
                for (int c = 0; c < 3; c++) b[r][c] -= f * b[col][c];
            }
        }
        for (int i = 0; i < 7; i++)
            for (int c = 0; c < 3; c++) sPara[i][c] = b[i][c] / a[i][i];
    }
    __syncthreads();

    if (tid < 48) {
        int t = tid / 3, ch = tid - t * 3;
        float s = 0.f;
#pragma unroll
        for (int cd = 0; cd < 7; cd++)
            s += design[(t * 7 + cd) * 2304 + y * 48 + x] * sPara[cd][ch];
        out[(t * 3 + ch) * 2304 + y * 48 + x] = s;
    }
}

// ---------------- launch ----------------
extern "C" void kernel_launch(void* const* d_in, const int* in_sizes, int n_in,
                              void* d_out, int out_size) {
    const float* input   = (const float*)d_in[0];
    const float* design  = (const float*)d_in[1];
    const float* fw0     = (const float*)d_in[2];
    const float* fb0     = (const float*)d_in[3];
    const float* fw_rest = (const float*)d_in[4];
    const float* fb_rest = (const float*)d_in[5];
    const float* ww0     = (const float*)d_in[6];
    const float* wb0     = (const float*)d_in[7];
    const float* ww_mid  = (const float*)d_in[8];
    const float* wb_mid  = (const float*)d_in[9];
    const float* ww1     = (const float*)d_in[10];
    const float* wb1     = (const float*)d_in[11];
    const float* ww2     = (const float*)d_in[12];
    const float* wb2     = (const float*)d_in[13];
    float* out = (float*)d_out;

    float *full, *f0, *f1, *col, *g0, *g1, *h, *wm;
    cudaGetSymbolAddress((void**)&full, d_full);
    cudaGetSymbolAddress((void**)&f0, d_f0);
    cudaGetSymbolAddress((void**)&f1, d_f1);
    cudaGetSymbolAddress((void**)&col, d_colbuf);
    cudaGetSymbolAddress((void**)&g0, d_g0);
    cudaGetSymbolAddress((void**)&g1, d_g1);
    cudaGetSymbolAddress((void**)&h, d_h);
    cudaGetSymbolAddress((void**)&wm, d_wm);

    auto GEMM = [&](const float* A, const float* B, const float* bias, float* C,
                    int M, int N, int K, int act, int outPM) {
        dim3 grid((N + BN - 1) / BN, (M + BM - 1) / BM);
        gemm_kernel<<<grid, 256>>>(A, B, bias, C, M, N, K, act, outPM);
    };
    auto IM2COL = [&](const float* in, int C, int Hin, int Win, int Hout, int Wout,
                      int kh, int kw, int stride, int pad) {
        im2col_kernel<<<4096, 256>>>(in, col, C, Hin, Win, Hout, Wout, kh, kw, stride, pad);
    };

    // 1) assemble full-res image
    make_full_kernel<<<(10 * 192 * 192 + 255) / 256, 256>>>(input, full);

    // 2) feature network: 14 conv3x3 + lrelu at 192x192
    IM2COL(full, 10, 192, 192, 192, 192, 3, 3, 1, 1);
    GEMM(col, fw0, fb0, f0, 36864, 100, 90, 1, 0);
    const float* fin = f0;
    float* fout = f1;
    for (int i = 0; i < 13; i++) {
        IM2COL(fin, 100, 192, 192, 192, 192, 3, 3, 1, 1);
        GEMM(col, fw_rest + (size_t)i * 90000, fb_rest + i * 100, fout, 36864, 100, 900, 1, 0);
        const float* t = fin; fin = fout; fout = (float*)t;
    }

    // 3) weight network
    IM2COL(fin, 100, 192, 192, 48, 48, 4, 4, 4, 0);       // stride-4 4x4
    GEMM(col, ww0, wb0, g0, 2304, 1024, 1600, 1, 0);
    const float* gin = g0;
    float* gout = g1;
    for (int i = 0; i < 3; i++) {
        IM2COL(gin, 1024, 48, 48, 48, 48, 3, 3, 1, 1);
        GEMM(col, ww_mid + (size_t)i * 9437184, wb_mid + i * 1024, gout, 2304, 1024, 9216, 1, 0);
        const float* t = gin; gin = gout; gout = (float*)t;
    }
    IM2COL(gin, 1024, 48, 48, 48, 48, 1, 1, 1, 0);        // transpose for 1x1
    GEMM(col, ww1, wb1, h, 2304, 6272, 1024, 1, 0);
    IM2COL(h, 6272, 48, 48, 48, 48, 1, 1, 1, 0);          // transpose for 1x1
    GEMM(col, ww2, wb2, wm, 2304, 12544, 6272, 2, 1);     // tanh, PIXEL-major out

    // 4) per-pixel normal equations + solve + recombine
    solve_kernel<<<2304, 256>>>(wm, design, input, out);
}

// round 4
// speedup vs baseline: 1.5491x; 1.5491x over previous
#include <cuda_runtime.h>
#include <cuda_bf16.h>
#include <math.h>
#include <stdint.h>

// ---------------- scratch (static __device__, no runtime alloc) ----------------
__device__ float d_full[10 * 192 * 192];
__device__ float d_f0[100 * 192 * 192];
__device__ float d_f1[100 * 192 * 192];
__device__ float d_colbuf[36864 * 900];
__device__ float d_g0[1024 * 48 * 48];
__device__ float d_g1[1024 * 48 * 48];
__device__ float d_h[6272 * 48 * 48];
__device__ float d_wm[2304 * 12544];   // Wmap PIXEL-major [p][c]

// ---------------- helpers ----------------
__device__ __forceinline__ uint32_t smem_to_u32(const void* p) {
    uint32_t a;
    asm("{ .reg .u64 t; cvta.to.shared.u64 t, %1; cvt.u32.u64 %0, t; }" : "=r"(a) : "l"(p));
    return a;
}
__device__ __forceinline__ uint32_t pkbf2(float x, float y) {
    __nv_bfloat162 h = __floats2bfloat162_rn(x, y);
    return *reinterpret_cast<uint32_t*>(&h);
}
__device__ __forceinline__ void ldsm4(uint32_t* r, uint32_t addr) {
    asm volatile("ldmatrix.sync.aligned.m8n8.x4.shared.b16 {%0,%1,%2,%3}, [%4];"
                 : "=r"(r[0]), "=r"(r[1]), "=r"(r[2]), "=r"(r[3]) : "r"(addr));
}
__device__ __forceinline__ void ldsm2(uint32_t* r, uint32_t addr) {
    asm volatile("ldmatrix.sync.aligned.m8n8.x2.shared.b16 {%0,%1}, [%2];"
                 : "=r"(r[0]), "=r"(r[1]) : "r"(addr));
}
__device__ __forceinline__ void mma_bf16(float* c, const uint32_t* a, const uint32_t* b) {
    asm volatile(
        "mma.sync.aligned.m16n8k16.row.col.f32.bf16.bf16.f32 "
        "{%0,%1,%2,%3}, {%4,%5,%6,%7}, {%8,%9}, {%0,%1,%2,%3};"
        : "+f"(c[0]), "+f"(c[1]), "+f"(c[2]), "+f"(c[3])
        : "r"(a[0]), "r"(a[1]), "r"(a[2]), "r"(a[3]), "r"(b[0]), "r"(b[1]));
}
__device__ __forceinline__ uint32_t swz(uint32_t base, int r, int c) {
    uint32_t off = (uint32_t)(r * 128 + c * 2);
    return base + (off ^ ((off >> 3) & 0x70));
}

// ---------------- make_full: (16,10,48,48) tiles -> (10,192,192) ----------------
__global__ void make_full_kernel(const float* __restrict__ in, float* __restrict__ out) {
    int idx = blockIdx.x * blockDim.x + threadIdx.x;
    if (idx >= 10 * 192 * 192) return;
    int x = idx % 192;
    int y = (idx / 192) % 192;
    int c = idx / (192 * 192);
    int w = x >> 2, s2 = x & 3;
    int h = y >> 2, s1 = y & 3;
    int t = s1 * 4 + s2;
    out[idx] = in[((t * 10 + c) * 48 + h) * 48 + w];
}

// ---------------- im2col, compile-time kernel window ----------------
template <int KH, int KW>
__global__ void im2col_k(const float* __restrict__ in, float* __restrict__ col,
                         int C, int Hin, int Win, int Wout, int stride, int pad) {
    const int m = blockIdx.y;
    const int k = blockIdx.x * blockDim.x + threadIdx.x;
    const int K = C * KH * KW;
    if (k >= K) return;
    const int x = m % Wout, y = m / Wout;
    const int j = k % KW;
    const int i = (k / KW) % KH;
    const int c = k / (KW * KH);
    const int iy = y * stride + i - pad;
    const int ix = x * stride + j - pad;
    float v = 0.f;
    if ((unsigned)iy < (unsigned)Hin && (unsigned)ix < (unsigned)Win)
        v = in[(c * Hin + iy) * Win + ix];
    col[(size_t)m * K + k] = v;
}

// ---------------- tiled transpose: in[C][HW] -> out[HW][C] ----------------
__global__ void transpose_kernel(const float* __restrict__ in, float* __restrict__ out,
                                 int C, int HW) {
    __shared__ float t[32][33];
    int hw0 = blockIdx.x * 32, c0 = blockIdx.y * 32;
    int tx = threadIdx.x, ty = threadIdx.y;
#pragma unroll
    for (int j = 0; j < 32; j += 8) {
        int c = c0 + ty + j, hw = hw0 + tx;
        t[ty + j][tx] = (c < C && hw < HW) ? in[(size_t)c * HW + hw] : 0.f;
    }
    __syncthreads();
#pragma unroll
    for (int j = 0; j < 32; j += 8) {
        int hw = hw0 + ty + j, c = c0 + tx;
        if (hw < HW && c < C) out[(size_t)hw * C + c] = t[tx][ty + j];
    }
}

// ---------------- bf16-split mma.sync GEMM ----------------
// C = A[M][K] * B[N][K]^T + bias, via Ah*Bh + Ah*Bl + Al*Bh (fp32 accumulate).
// act: 0 none, 1 lrelu(0.01), 2 tanh.  outPM: 1 -> C[m][n] row-major, else C[n][m].
#define TBM 128
#define TBN 128
#define TKC 64
#define TILE_BYTES 16384                 // 128 rows x 128 bytes (64 bf16)
#define GEMM_SMEM (8 * TILE_BYTES)       // 2 stages x {Ah,Al,Bh,Bl}

__global__ __launch_bounds__(256, 1) void tc_gemm_kernel(
    const float* __restrict__ A, const float* __restrict__ B,
    const float* __restrict__ bias, float* __restrict__ C,
    int M, int N, int K, int act, int outPM) {
    extern __shared__ __align__(1024) char smem[];
    const uint32_t sb = smem_to_u32(smem);
    const int tid = threadIdx.x;
    const int wid = tid >> 5;
    const int lane = tid & 31;
    const int m0 = blockIdx.y * TBM, n0 = blockIdx.x * TBN;
    const int wm = (wid >> 2) * 64;      // warp m offset: 0 / 64
    const int wn = (wid & 3) * 32;       // warp n offset: 0/32/64/96

    // ---- loader indexing: each thread owns one tile row (m or n) and a 32-wide k slice
    const int row = tid >> 1;            // 0..127
    const int kq = (tid & 1) * 32;       // 0 / 32
    const bool aOk = (m0 + row) < M;
    const bool bOk = (n0 + row) < N;
    const float* Ap = A + (size_t)(m0 + row) * K;
    const float* Bp = B + (size_t)(n0 + row) * K;
    const bool vec = ((K & 3) == 0);
    const int nk = (K + TKC - 1) / TKC;

    float acc[4][4][4];
#pragma unroll
    for (int i = 0; i < 4; i++)
#pragma unroll
        for (int j = 0; j < 4; j++)
#pragma unroll
            for (int q = 0; q < 4; q++) acc[i][j][q] = 0.f;

    float va[32], vb[32];

    auto loadChunk = [&](int c) {
        const int kb = c * TKC + kq;
        if (vec) {
#pragma unroll
            for (int g = 0; g < 8; g++) {
                int kk = kb + g * 4;
                float4 ta = make_float4(0.f, 0.f, 0.f, 0.f);
                float4 tb = ta;
                if (aOk && kk < K) ta = *(const float4*)(Ap + kk);
                if (bOk && kk < K) tb = *(const float4*)(Bp + kk);
                va[g * 4 + 0] = ta.x; va[g * 4 + 1] = ta.y;
                va[g * 4 + 2] = ta.z; va[g * 4 + 3] = ta.w;
                vb[g * 4 + 0] = tb.x; vb[g * 4 + 1] = tb.y;
                vb[g * 4 + 2] = tb.z; vb[g * 4 + 3] = tb.w;
            }
        } else {
#pragma unroll 4
            for (int j = 0; j < 32; j++) {
                int kk = kb + j;
                va[j] = (aOk && kk < K) ? Ap[kk] : 0.f;
                vb[j] = (bOk && kk < K) ? Bp[kk] : 0.f;
            }
        }
    };

    auto storeChunk = [&](int b) {
        const uint32_t tAh = sb + (b * 4 + 0) * TILE_BYTES;
        const uint32_t tAl = sb + (b * 4 + 1) * TILE_BYTES;
        const uint32_t tBh = sb + (b * 4 + 2) * TILE_BYTES;
        const uint32_t tBl = sb + (b * 4 + 3) * TILE_BYTES;
#pragma unroll
        for (int g = 0; g < 4; g++) {
            uint32_t ah[4], al[4], bh[4], bl[4];
#pragma unroll
            for (int j = 0; j < 4; j++) {
                float a0 = va[g * 8 + j * 2], a1 = va[g * 8 + j * 2 + 1];
                float b0 = vb[g * 8 + j * 2], b1 = vb[g * 8 + j * 2 + 1];
                __nv_bfloat16 ha0 = __float2bfloat16(a0), ha1 = __float2bfloat16(a1);
                __nv_bfloat16 hb0 = __float2bfloat16(b0), hb1 = __float2bfloat16(b1);
                float la0 = a0 - __bfloat162float(ha0), la1 = a1 - __bfloat162float(ha1);
                float lb0 = b0 - __bfloat162float(hb0), lb1 = b1 - __bfloat162float(hb1);
                __nv_bfloat162 pa; pa.x = ha0; pa.y = ha1;
                __nv_bfloat162 pb; pb.x = hb0; pb.y = hb1;
                ah[j] = *reinterpret_cast<uint32_t*>(&pa);
                bh[j] = *reinterpret_cast<uint32_t*>(&pb);
                al[j] = pkbf2(la0, la1);
                bl[j] = pkbf2(lb0, lb1);
            }
            uint32_t sw = swz(0, row, kq + g * 8);
            asm volatile("st.shared.v4.b32 [%0], {%1,%2,%3,%4};" ::
                         "r"(tAh + sw), "r"(ah[0]), "r"(ah[1]), "r"(ah[2]), "r"(ah[3]) : "memory");
            asm volatile("st.shared.v4.b32 [%0], {%1,%2,%3,%4};" ::
                         "r"(tAl + sw), "r"(al[0]), "r"(al[1]), "r"(al[2]), "r"(al[3]) : "memory");
            asm volatile("st.shared.v4.b32 [%0], {%1,%2,%3,%4};" ::
                         "r"(tBh + sw), "r"(bh[0]), "r"(bh[1]), "r"(bh[2]), "r"(bh[3]) : "memory");
            asm volatile("st.shared.v4.b32 [%0], {%1,%2,%3,%4};" ::
                         "r"(tBl + sw), "r"(bl[0]), "r"(bl[1]), "r"(bl[2]), "r"(bl[3]) : "memory");
        }
    };

    auto compute = [&](int b) {
        const uint32_t tAh = sb + (b * 4 + 0) * TILE_BYTES;
        const uint32_t tAl = sb + (b * 4 + 1) * TILE_BYTES;
        const uint32_t tBh = sb + (b * 4 + 2) * TILE_BYTES;
        const uint32_t tBl = sb + (b * 4 + 3) * TILE_BYTES;
        const int rA = wm + (lane & 15);
        const int cA = (lane >> 4) * 8;
        const int rB = wn + (lane & 7);
        const int cB = ((lane >> 3) & 1) * 8;
#pragma unroll
        for (int s = 0; s < 4; s++) {
            const int kk = s * 16;
            uint32_t aH[4][4], aL[4][4], bH[4][2], bL[4][2];
#pragma unroll
            for (int mt = 0; mt < 4; mt++) {
                ldsm4(aH[mt], swz(tAh, rA + mt * 16, kk + cA));
                ldsm4(aL[mt], swz(tAl, rA + mt * 16, kk + cA));
            }
#pragma unroll
            for (int nt = 0; nt < 4; nt++) {
                ldsm2(bH[nt], swz(tBh, rB + nt * 8, kk + cB));
                ldsm2(bL[nt], swz(tBl, rB + nt * 8, kk + cB));
            }
#pragma unroll
            for (int mt = 0; mt < 4; mt++)
#pragma unroll
                for (int nt = 0; nt < 4; nt++)
                    mma_bf16(acc[mt][nt], aH[mt], bH[nt]);
#pragma unroll
            for (int mt = 0; mt < 4; mt++)
#pragma unroll
                for (int nt = 0; nt < 4; nt++)
                    mma_bf16(acc[mt][nt], aH[mt], bL[nt]);
#pragma unroll
            for (int mt = 0; mt < 4; mt++)
#pragma unroll
                for (int nt = 0; nt < 4; nt++)
                    mma_bf16(acc[mt][nt], aL[mt], bH[nt]);
        }
    };

    // ---- pipeline ----
    loadChunk(0);
    storeChunk(0);
    __syncthreads();
    for (int c = 0; c < nk; c++) {
        if (c + 1 < nk) loadChunk(c + 1);
        compute(c & 1);
        if (c + 1 < nk) storeChunk((c + 1) & 1);
        __syncthreads();
    }

    // ---- epilogue ----
    const int er = lane >> 2;            // 0..7
    const int ec = (lane & 3) * 2;       // 0,2,4,6
#pragma unroll
    for (int mt = 0; mt < 4; mt++) {
#pragma unroll
        for (int nt = 0; nt < 4; nt++) {
#pragma unroll
            for (int q = 0; q < 4; q++) {
                int m = m0 + wm + mt * 16 + er + (q >= 2 ? 8 : 0);
                int n = n0 + wn + nt * 8 + ec + (q & 1);
                if (m < M && n < N) {
                    float v = acc[mt][nt][q] + bias[n];
                    if (act == 1) v = v > 0.f ? v : 0.01f * v;
                    else if (act == 2) v = tanhf(v);
                    if (outPM) C[(size_t)m * N + n] = v;
                    else       C[(size_t)n * M + m] = v;
                }
            }
        }
    }
}

// ---------------- per-pixel normal-equations solve ----------------
__global__ __launch_bounds__(256) void solve_kernel(
    const float* __restrict__ wmap, const float* __restrict__ design,
    const float* __restrict__ input, float* __restrict__ out) {
    const int p = blockIdx.x;
    const int y = p / 48, x = p % 48;
    const int tid = threadIdx.x;
    __shared__ float sWm[16][17];
    __shared__ float sM[16][17];
    __shared__ float sX[16][8];
    __shared__ float sY[16][4];
    __shared__ float sXTW[7][16];
    __shared__ float sA[49];
    __shared__ float sB[21];
    __shared__ float sPara[7][3];

    if (tid < 49) sA[tid] = 0.f;
    if (tid < 21) sB[tid] = 0.f;
    const int t1 = tid >> 4, t2 = tid & 15;
    const float* wp = wmap + (size_t)p * 12544;

    for (int ni = 0; ni < 49; ni++) {
        int ny = y + ni / 7 - 3;
        int nx = x + ni % 7 - 3;
        bool inb = ((unsigned)ny < 48u) && ((unsigned)nx < 48u);
        __syncthreads();
        sWm[t1][t2] = wp[ni * 256 + tid];
        if (tid < 112) {
            int t = tid / 7, cd = tid - t * 7;
            sX[t][cd] = inb ? design[(t * 7 + cd) * 2304 + ny * 48 + nx] : 0.f;
        }
        if (tid >= 128 && tid < 176) {
            int r = tid - 128;
            int t = r / 3, ch = r - t * 3;
            sY[t][ch] = inb ? input[(t * 10 + ch) * 2304 + ny * 48 + nx] : 0.f;
        }
        __syncthreads();
        float s = (t1 == t2) ? 1.f : 0.f;
#pragma unroll
        for (int k = 0; k < 16; k++) s += sWm[t1][k] * sWm[t2][k];
        sM[t1][t2] = s;
        __syncthreads();
        if (tid < 112) {
            int cd = tid >> 4, t = tid & 15;
            float v = 0.f;
#pragma unroll
            for (int k = 0; k < 16; k++) v += sX[k][cd] * sM[k][t];
            sXTW[cd][t] = v;
        }
        __syncthreads();
        if (tid < 49) {
            int cd = tid / 7, ce = tid - cd * 7;
            float v = 0.f;
#pragma unroll
            for (int t = 0; t < 16; t++) v += sXTW[cd][t] * sX[t][ce];
            sA[tid] += v;
        }
        if (tid >= 64 && tid < 85) {
            int r = tid - 64;
            int cd = r / 3, ch = r - cd * 3;
            float v = 0.f;
#pragma unroll
            for (int t = 0; t < 16; t++) v += sXTW[cd][t] * sY[t][ch];
            sB[r] += v;
        }
    }
    __syncthreads();

    if (tid == 0) {
        float a[7][7], b[7][3];
        for (int i = 0; i < 7; i++) {
            for (int j = 0; j < 7; j++) a[i][j] = sA[i * 7 + j];
            a[i][i] += 0.01f;
            for (int c = 0; c < 3; c++) b[i][c] = sB[i * 3 + c];
        }
        for (int col = 0; col < 7; col++) {
            int piv = col;
            float mx = fabsf(a[col][col]);
            for (int r = col + 1; r < 7; r++) {
                float v = fabsf(a[r][col]);
                if (v > mx) { mx = v; piv = r; }
            }
            if (piv != col) {
                for (int c2 = 0; c2 < 7; c2++) { float t = a[col][c2]; a[col][c2] = a[piv][c2]; a[piv][c2] = t; }
                for (int c2 = 0; c2 < 3; c2++) { float t = b[col][c2]; b[col][c2] = b[piv][c2]; b[piv][c2] = t; }
            }
            float inv = 1.f / a[col][col];
            for (int r = 0; r < 7; r++) {
                if (r == col) continue;
                float f = a[r][col] * inv;
                for (int c2 = col; c2 < 7; c2++) a[r][c2] -= f * a[col][c2];
                for (int c2 = 0; c2 < 3; c2++) b[r][c2] -= f * b[col][c2];
            }
        }
        for (int i = 0; i < 7; i++)
            for (int c2 = 0; c2 < 3; c2++) sPara[i][c2] = b[i][c2] / a[i][i];
    }
    __syncthreads();

    if (tid < 48) {
        int t = tid / 3, ch = tid - t * 3;
        float s = 0.f;
#pragma unroll
        for (int cd = 0; cd < 7; cd++)
            s += design[(t * 7 + cd) * 2304 + y * 48 + x] * sPara[cd][ch];
        out[(t * 3 + ch) * 2304 + y * 48 + x] = s;
    }
}

// ---------------- launch ----------------
extern "C" void kernel_launch(void* const* d_in, const int* in_sizes, int n_in,
                              void* d_out, int out_size) {
    const float* input   = (const float*)d_in[0];
    const float* design  = (const float*)d_in[1];
    const float* fw0     = (const float*)d_in[2];
    const float* fb0     = (const float*)d_in[3];
    const float* fw_rest = (const float*)d_in[4];
    const float* fb_rest = (const float*)d_in[5];
    const float* ww0     = (const float*)d_in[6];
    const float* wb0     = (const float*)d_in[7];
    const float* ww_mid  = (const float*)d_in[8];
    const float* wb_mid  = (const float*)d_in[9];
    const float* ww1     = (const float*)d_in[10];
    const float* wb1     = (const float*)d_in[11];
    const float* ww2     = (const float*)d_in[12];
    const float* wb2     = (const float*)d_in[13];
    float* out = (float*)d_out;

    float *full, *f0, *f1, *col, *g0, *g1, *h, *wm;
    cudaGetSymbolAddress((void**)&full, d_full);
    cudaGetSymbolAddress((void**)&f0, d_f0);
    cudaGetSymbolAddress((void**)&f1, d_f1);
    cudaGetSymbolAddress((void**)&col, d_colbuf);
    cudaGetSymbolAddress((void**)&g0, d_g0);
    cudaGetSymbolAddress((void**)&g1, d_g1);
    cudaGetSymbolAddress((void**)&h, d_h);
    cudaGetSymbolAddress((void**)&wm, d_wm);

    cudaFuncSetAttribute(tc_gemm_kernel, cudaFuncAttributeMaxDynamicSharedMemorySize, GEMM_SMEM);

    auto GEMM = [&](const float* A, const float* B, const float* bias, float* C,
                    int M, int N, int K, int act, int outPM) {
        dim3 grid((N + TBN - 1) / TBN, (M + TBM - 1) / TBM);
        tc_gemm_kernel<<<grid, 256, GEMM_SMEM>>>(A, B, bias, C, M, N, K, act, outPM);
    };

    // 1) assemble full-res image
    make_full_kernel<<<(10 * 192 * 192 + 255) / 256, 256>>>(input, full);

    // 2) feature network: 14 conv3x3 + lrelu at 192x192
    {
        dim3 g((10 * 9 + 255) / 256, 36864);
        im2col_k<3, 3><<<g, 256>>>(full, col, 10, 192, 192, 192, 1, 1);
    }
    GEMM(col, fw0, fb0, f0, 36864, 100, 90, 1, 0);
    const float* fin = f0;
    float* fout = f1;
    for (int i = 0; i < 13; i++) {
        dim3 g((100 * 9 + 255) / 256, 36864);
        im2col_k<3, 3><<<g, 256>>>(fin, col, 100, 192, 192, 192, 1, 1);
        GEMM(col, fw_rest + (size_t)i * 90000, fb_rest + i * 100, fout, 36864, 100, 900, 1, 0);
        const float* t = fin; fin = fout; fout = (float*)t;
    }

    // 3) weight network
    {
        dim3 g((100 * 16 + 255) / 256, 2304);
        im2col_k<4, 4><<<g, 256>>>(fin, col, 100, 192, 192, 48, 4, 0);
    }
    GEMM(col, ww0, wb0, g0, 2304, 1024, 1600, 1, 0);
    const float* gin = g0;
    float* gout = g1;
    for (int i = 0; i < 3; i++) {
        dim3 g((1024 * 9 + 255) / 256, 2304);
        im2col_k<3, 3><<<g, 256>>>(gin, col, 1024, 48, 48, 48, 1, 1);
        GEMM(col, ww_mid + (size_t)i * 9437184, wb_mid + i * 1024, gout, 2304, 1024, 9216, 1, 0);
        const float* t = gin; gin = gout; gout = (float*)t;
    }
    {   // transpose g [1024][2304] -> col [2304][1024]
        dim3 g((2304 + 31) / 32, (1024 + 31) / 32);
        transpose_kernel<<<g, dim3(32, 8)>>>(gin, col, 1024, 2304);
    }
    GEMM(col, ww1, wb1, h, 2304, 6272, 1024, 1, 0);
    {   // transpose h [6272][2304] -> col [2304][6272]
        dim3 g((2304 + 31) / 32, (6272 + 31) / 32);
        transpose_kernel<<<g, dim3(32, 8)>>>(h, col, 6272, 2304);
    }
    GEMM(col, ww2, wb2, wm, 2304, 12544, 6272, 2, 1);   // tanh, PIXEL-major out

    // 4) per-pixel normal equations + solve + recombine
    solve_kernel<<<2304, 256>>>(wm, design, input, out);
}

// round 5
// speedup vs baseline: 2.4699x; 1.5944x over previous
#include <cuda_runtime.h>
#include <cuda_bf16.h>
#include <math.h>
#include <stdint.h>

// ---------------- scratch (static __device__, no runtime alloc) ----------------
__device__ float d_full[10 * 192 * 192];
__device__ float d_f0[100 * 192 * 192];
__device__ float d_f1[100 * 192 * 192];
__device__ float d_g0[1024 * 48 * 48];
__device__ float d_g1[1024 * 48 * 48];
__device__ float d_h[6272 * 48 * 48];
__device__ float d_wm[2304 * 12544];                 // Wmap PIXEL-major [p][c]
__device__ __nv_bfloat16 d_colh[36864 * 960];        // A operand hi (max 35.4M)
__device__ __nv_bfloat16 d_coll[36864 * 960];        // A operand lo
__device__ __nv_bfloat16 d_wbh[12544 * 6272];        // B operand hi (max 78.7M)
__device__ __nv_bfloat16 d_wbl[12544 * 6272];        // B operand lo

// ---------------- helpers ----------------
__device__ __forceinline__ uint32_t smem_to_u32(const void* p) {
    uint32_t a;
    asm("{ .reg .u64 t; cvta.to.shared.u64 t, %1; cvt.u32.u64 %0, t; }" : "=r"(a) : "l"(p));
    return a;
}
__device__ __forceinline__ void ldsm4(uint32_t* r, uint32_t addr) {
    asm volatile("ldmatrix.sync.aligned.m8n8.x4.shared.b16 {%0,%1,%2,%3}, [%4];"
                 : "=r"(r[0]), "=r"(r[1]), "=r"(r[2]), "=r"(r[3]) : "r"(addr));
}
__device__ __forceinline__ void ldsm2(uint32_t* r, uint32_t addr) {
    asm volatile("ldmatrix.sync.aligned.m8n8.x2.shared.b16 {%0,%1}, [%2];"
                 : "=r"(r[0]), "=r"(r[1]) : "r"(addr));
}
__device__ __forceinline__ void mma_bf16(float* c, const uint32_t* a, const uint32_t* b) {
    asm volatile(
        "mma.sync.aligned.m16n8k16.row.col.f32.bf16.bf16.f32 "
        "{%0,%1,%2,%3}, {%4,%5,%6,%7}, {%8,%9}, {%0,%1,%2,%3};"
        : "+f"(c[0]), "+f"(c[1]), "+f"(c[2]), "+f"(c[3])
        : "r"(a[0]), "r"(a[1]), "r"(a[2]), "r"(a[3]), "r"(b[0]), "r"(b[1]));
}
__device__ __forceinline__ uint32_t swz(uint32_t base, int r, int c) {
    uint32_t off = (uint32_t)(r * 128 + c * 2);
    return base + (off ^ ((off >> 3) & 0x70));
}
__device__ __forceinline__ void cp16(uint32_t dst, const void* src, uint32_t sz) {
    asm volatile("cp.async.cg.shared.global [%0], [%1], 16, %2;"
                 :: "r"(dst), "l"(src), "r"(sz) : "memory");
}

// ---------------- make_full: (16,10,48,48) tiles -> (10,192,192) ----------------
__global__ void make_full_kernel(const float* __restrict__ in, float* __restrict__ out) {
    int idx = blockIdx.x * blockDim.x + threadIdx.x;
    if (idx >= 10 * 192 * 192) return;
    int x = idx % 192;
    int y = (idx / 192) % 192;
    int c = idx / (192 * 192);
    int w = x >> 2, s2 = x & 3;
    int h = y >> 2, s1 = y & 3;
    int t = s1 * 4 + s2;
    out[idx] = in[((t * 10 + c) * 48 + h) * 48 + w];
}

// ---------------- im2col emitting split bf16, K padded to Kp ----------------
template <int KH, int KW>
__global__ void im2col_split_k(const float* __restrict__ in,
                               __nv_bfloat16* __restrict__ ch, __nv_bfloat16* __restrict__ cl,
                               int C, int Hin, int Win, int Wout, int stride, int pad,
                               int K, int Kp) {
    const int m = blockIdx.y;
    const int k = blockIdx.x * blockDim.x + threadIdx.x;
    if (k >= Kp) return;
    float v = 0.f;
    if (k < K) {
        const int x = m % Wout, y = m / Wout;
        const int j = k % KW;
        const int i = (k / KW) % KH;
        const int c = k / (KW * KH);
        const int iy = y * stride + i - pad;
        const int ix = x * stride + j - pad;
        if ((unsigned)iy < (unsigned)Hin && (unsigned)ix < (unsigned)Win)
            v = in[(c * Hin + iy) * Win + ix];
    }
    __nv_bfloat16 hi = __float2bfloat16(v);
    __nv_bfloat16 lo = __float2bfloat16(v - __bfloat162float(hi));
    ch[(size_t)m * Kp + k] = hi;
    cl[(size_t)m * Kp + k] = lo;
}

// ---------------- weight split: fp32 [rows][K] -> bf16 h/l [rows][Kp] ----------------
__global__ void split_w_kernel(const float* __restrict__ in,
                               __nv_bfloat16* __restrict__ oh, __nv_bfloat16* __restrict__ ol,
                               int K, int Kp) {
    const int r = blockIdx.y;
    const int k = blockIdx.x * blockDim.x + threadIdx.x;
    if (k >= Kp) return;
    float v = (k < K) ? in[(size_t)r * K + k] : 0.f;
    __nv_bfloat16 hi = __float2bfloat16(v);
    __nv_bfloat16 lo = __float2bfloat16(v - __bfloat162float(hi));
    oh[(size_t)r * Kp + k] = hi;
    ol[(size_t)r * Kp + k] = lo;
}

// ---------------- transpose + split: in[C][HW] fp32 -> out[HW][C] bf16 h/l ----------------
__global__ void transpose_split_kernel(const float* __restrict__ in,
                                       __nv_bfloat16* __restrict__ oh, __nv_bfloat16* __restrict__ ol,
                                       int C, int HW) {
    __shared__ float t[32][33];
    int hw0 = blockIdx.x * 32, c0 = blockIdx.y * 32;
    int tx = threadIdx.x, ty = threadIdx.y;
#pragma unroll
    for (int j = 0; j < 32; j += 8) {
        int c = c0 + ty + j, hw = hw0 + tx;
        t[ty + j][tx] = (c < C && hw < HW) ? in[(size_t)c * HW + hw] : 0.f;
    }
    __syncthreads();
#pragma unroll
    for (int j = 0; j < 32; j += 8) {
        int hw = hw0 + ty + j, c = c0 + tx;
        if (hw < HW && c < C) {
            float v = t[tx][ty + j];
            __nv_bfloat16 hi = __float2bfloat16(v);
            __nv_bfloat16 lo = __float2bfloat16(v - __bfloat162float(hi));
            oh[(size_t)hw * C + c] = hi;
            ol[(size_t)hw * C + c] = lo;
        }
    }
}

// ---------------- bf16-split mma.sync GEMM (pre-split operands, cp.async loader) ----------
// C = A[M][Kp]*B[N][Kp]^T + bias; 3 passes Ah*Bh + Ah*Bl + Al*Bh, fp32 accumulate.
// act: 0 none, 1 lrelu(0.01), 2 tanh.  outPM: 1 -> C[m][n] row-major, else C[n][m].
#define TBM 128
#define TBN 128
#define TKC 64
#define TILE_BYTES 16384                 // 128 rows x 64 bf16 (128B)
#define GEMM_SMEM (8 * TILE_BYTES)       // 2 stages x {Ah,Al,Bh,Bl}

__global__ __launch_bounds__(256, 1) void tc_gemm_kernel(
    const __nv_bfloat16* __restrict__ Ah, const __nv_bfloat16* __restrict__ Al,
    const __nv_bfloat16* __restrict__ Bh, const __nv_bfloat16* __restrict__ Bl,
    const float* __restrict__ bias, float* __restrict__ C,
    int M, int N, int Kp, int act, int outPM) {
    extern __shared__ __align__(1024) char smem[];
    const uint32_t sb = smem_to_u32(smem);
    const int tid = threadIdx.x;
    const int wid = tid >> 5;
    const int lane = tid & 31;
    const int m0 = blockIdx.y * TBM, n0 = blockIdx.x * TBN;
    const int wm = (wid >> 2) * 64;
    const int wn = (wid & 3) * 32;

    const int row = tid >> 1;            // 0..127
    const int kq = (tid & 1) * 32;       // 0 / 32
    const uint32_t aSz = ((m0 + row) < M) ? 16u : 0u;
    const uint32_t bSz = ((n0 + row) < N) ? 16u : 0u;
    const size_t arow = (size_t)((m0 + row) < M ? (m0 + row) : (M - 1));
    const size_t brow = (size_t)((n0 + row) < N ? (n0 + row) : (N - 1));
    const __nv_bfloat16* pAh = Ah + arow * Kp + kq;
    const __nv_bfloat16* pAl = Al + arow * Kp + kq;
    const __nv_bfloat16* pBh = Bh + brow * Kp + kq;
    const __nv_bfloat16* pBl = Bl + brow * Kp + kq;
    const int nk = Kp / TKC;

    float acc[4][4][4];
#pragma unroll
    for (int i = 0; i < 4; i++)
#pragma unroll
        for (int j = 0; j < 4; j++)
#pragma unroll
            for (int q = 0; q < 4; q++) acc[i][j][q] = 0.f;

    auto issueLoads = [&](int c) {
        const int b = c & 1;
        const uint32_t tAh = sb + (b * 4 + 0) * TILE_BYTES;
        const uint32_t tAl = sb + (b * 4 + 1) * TILE_BYTES;
        const uint32_t tBh = sb + (b * 4 + 2) * TILE_BYTES;
        const uint32_t tBl = sb + (b * 4 + 3) * TILE_BYTES;
        const int kb = c * TKC;
#pragma unroll
        for (int j = 0; j < 4; j++) {
            uint32_t d = swz(0, row, kq + j * 8);
            cp16(tAh + d, pAh + kb + j * 8, aSz);
            cp16(tAl + d, pAl + kb + j * 8, aSz);
            cp16(tBh + d, pBh + kb + j * 8, bSz);
            cp16(tBl + d, pBl + kb + j * 8, bSz);
        }
        asm volatile("cp.async.commit_group;" ::: "memory");
    };

    auto compute = [&](int b) {
        const uint32_t tAh = sb + (b * 4 + 0) * TILE_BYTES;
        const uint32_t tAl = sb + (b * 4 + 1) * TILE_BYTES;
        const uint32_t tBh = sb + (b * 4 + 2) * TILE_BYTES;
        const uint32_t tBl = sb + (b * 4 + 3) * TILE_BYTES;
        const int rA = wm + (lane & 15);
        const int cA = (lane >> 4) * 8;
        const int rB = wn + (lane & 7);
        const int cB = ((lane >> 3) & 1) * 8;
#pragma unroll
        for (int s = 0; s < 4; s++) {
            const int kk = s * 16;
            uint32_t aH[4][4], aL[4][4], bH[4][2], bL[4][2];
#pragma unroll
            for (int mt = 0; mt < 4; mt++) {
                ldsm4(aH[mt], swz(tAh, rA + mt * 16, kk + cA));
                ldsm4(aL[mt], swz(tAl, rA + mt * 16, kk + cA));
            }
#pragma unroll
            for (int nt = 0; nt < 4; nt++) {
                ldsm2(bH[nt], swz(tBh, rB + nt * 8, kk + cB));
                ldsm2(bL[nt], swz(tBl, rB + nt * 8, kk + cB));
            }
#pragma unroll
            for (int mt = 0; mt < 4; mt++)
#pragma unroll
                for (int nt = 0; nt < 4; nt++)
                    mma_bf16(acc[mt][nt], aH[mt], bH[nt]);
#pragma unroll
            for (int mt = 0; mt < 4; mt++)
#pragma unroll
                for (int nt = 0; nt < 4; nt++)
                    mma_bf16(acc[mt][nt], aH[mt], bL[nt]);
#pragma unroll
            for (int mt = 0; mt < 4; mt++)
#pragma unroll
                for (int nt = 0; nt < 4; nt++)
                    mma_bf16(acc[mt][nt], aL[mt], bH[nt]);
        }
    };

    // ---- pipeline ----
    issueLoads(0);
    for (int c = 0; c < nk; c++) {
        if (c + 1 < nk) {
            issueLoads(c + 1);
            asm volatile("cp.async.wait_group 1;" ::: "memory");
        } else {
            asm volatile("cp.async.wait_group 0;" ::: "memory");
        }
        __syncthreads();
        compute(c & 1);
        __syncthreads();
    }

    // ---- epilogue ----
    const int er = lane >> 2;
    const int ec = (lane & 3) * 2;
#pragma unroll
    for (int mt = 0; mt < 4; mt++) {
#pragma unroll
        for (int nt = 0; nt < 4; nt++) {
#pragma unroll
            for (int q = 0; q < 4; q++) {
                int m = m0 + wm + mt * 16 + er + (q >= 2 ? 8 : 0);
                int n = n0 + wn + nt * 8 + ec + (q & 1);
                if (m < M && n < N) {
                    float v = acc[mt][nt][q] + bias[n];
                    if (act == 1) v = v > 0.f ? v : 0.01f * v;
                    else if (act == 2) v = tanhf(v);
                    if (outPM) C[(size_t)m * N + n] = v;
                    else       C[(size_t)n * M + m] = v;
                }
            }
        }
    }
}

// ---------------- per-pixel normal-equations solve ----------------
__global__ __launch_bounds__(256) void solve_kernel(
    const float* __restrict__ wmap, const float* __restrict__ design,
    const float* __restrict__ input, float* __restrict__ out) {
    const int p = blockIdx.x;
    const int y = p / 48, x = p % 48;
    const int tid = threadIdx.x;
    __shared__ float sWm[16][17];
    __shared__ float sM[16][17];
    __shared__ float sX[16][8];
    __shared__ float sY[16][4];
    __shared__ float sXTW[7][16];
    __shared__ float sA[49];
    __shared__ float sB[21];
    __shared__ float sPara[7][3];

    if (tid < 49) sA[tid] = 0.f;
    if (tid < 21) sB[tid] = 0.f;
    const int t1 = tid >> 4, t2 = tid & 15;
    const float* wp = wmap + (size_t)p * 12544;

    for (int ni = 0; ni < 49; ni++) {
        int ny = y + ni / 7 - 3;
        int nx = x + ni % 7 - 3;
        bool inb = ((unsigned)ny < 48u) && ((unsigned)nx < 48u);
        __syncthreads();
        sWm[t1][t2] = wp[ni * 256 + tid];
        if (tid < 112) {
            int t = tid / 7, cd = tid - t * 7;
            sX[t][cd] = inb ? design[(t * 7 + cd) * 2304 + ny * 48 + nx] : 0.f;
        }
        if (tid >= 128 && tid < 176) {
            int r = tid - 128;
            int t = r / 3, ch = r - t * 3;
            sY[t][ch] = inb ? input[(t * 10 + ch) * 2304 + ny * 48 + nx] : 0.f;
        }
        __syncthreads();
        float s = (t1 == t2) ? 1.f : 0.f;
#pragma unroll
        for (int k = 0; k < 16; k++) s += sWm[t1][k] * sWm[t2][k];
        sM[t1][t2] = s;
        __syncthreads();
        if (tid < 112) {
            int cd = tid >> 4, t = tid & 15;
            float v = 0.f;
#pragma unroll
            for (int k = 0; k < 16; k++) v += sX[k][cd] * sM[k][t];
            sXTW[cd][t] = v;
        }
        __syncthreads();
        if (tid < 49) {
            int cd = tid / 7, ce = tid - cd * 7;
            float v = 0.f;
#pragma unroll
            for (int t = 0; t < 16; t++) v += sXTW[cd][t] * sX[t][ce];
            sA[tid] += v;
        }
        if (tid >= 64 && tid < 85) {
            int r = tid - 64;
            int cd = r / 3, ch = r - cd * 3;
            float v = 0.f;
#pragma unroll
            for (int t = 0; t < 16; t++) v += sXTW[cd][t] * sY[t][ch];
            sB[r] += v;
        }
    }
    __syncthreads();

    if (tid == 0) {
        float a[7][7], b[7][3];
        for (int i = 0; i < 7; i++) {
            for (int j = 0; j < 7; j++) a[i][j] = sA[i * 7 + j];
            a[i][i] += 0.01f;
            for (int c = 0; c < 3; c++) b[i][c] = sB[i * 3 + c];
        }
        for (int col = 0; col < 7; col++) {
            int piv = col;
            float mx = fabsf(a[col][col]);
            for (int r = col + 1; r < 7; r++) {
                float v = fabsf(a[r][col]);
                if (v > mx) { mx = v; piv = r; }
            }
            if (piv != col) {
                for (int c2 = 0; c2 < 7; c2++) { float t = a[col][c2]; a[col][c2] = a[piv][c2]; a[piv][c2] = t; }
                for (int c2 = 0; c2 < 3; c2++) { float t = b[col][c2]; b[col][c2] = b[piv][c2]; b[piv][c2] = t; }
            }
            float inv = 1.f / a[col][col];
            for (int r = 0; r < 7; r++) {
                if (r == col) continue;
                float f = a[r][col] * inv;
                for (int c2 = col; c2 < 7; c2++) a[r][c2] -= f * a[col][c2];
                for (int c2 = 0; c2 < 3; c2++) b[r][c2] -= f * b[col][c2];
            }
        }
        for (int i = 0; i < 7; i++)
            for (int c2 = 0; c2 < 3; c2++) sPara[i][c2] = b[i][c2] / a[i][i];
    }
    __syncthreads();

    if (tid < 48) {
        int t = tid / 3, ch = tid - t * 3;
        float s = 0.f;
#pragma unroll
        for (int cd = 0; cd < 7; cd++)
            s += design[(t * 7 + cd) * 2304 + y * 48 + x] * sPara[cd][ch];
        out[(t * 3 + ch) * 2304 + y * 48 + x] = s;
    }
}

// ---------------- launch ----------------
extern "C" void kernel_launch(void* const* d_in, const int* in_sizes, int n_in,
                              void* d_out, int out_size) {
    const float* input   = (const float*)d_in[0];
    const float* design  = (const float*)d_in[1];
    const float* fw0     = (const float*)d_in[2];
    const float* fb0     = (const float*)d_in[3];
    const float* fw_rest = (const float*)d_in[4];
    const float* fb_rest = (const float*)d_in[5];
    const float* ww0     = (const float*)d_in[6];
    const float* wb0     = (const float*)d_in[7];
    const float* ww_mid  = (const float*)d_in[8];
    const float* wb_mid  = (const float*)d_in[9];
    const float* ww1     = (const float*)d_in[10];
    const float* wb1     = (const float*)d_in[11];
    const float* ww2     = (const float*)d_in[12];
    const float* wb2     = (const float*)d_in[13];
    float* out = (float*)d_out;

    float *full, *f0, *f1, *g0, *g1, *h, *wm;
    __nv_bfloat16 *colh, *coll, *wbh, *wbl;
    cudaGetSymbolAddress((void**)&full, d_full);
    cudaGetSymbolAddress((void**)&f0, d_f0);
    cudaGetSymbolAddress((void**)&f1, d_f1);
    cudaGetSymbolAddress((void**)&g0, d_g0);
    cudaGetSymbolAddress((void**)&g1, d_g1);
    cudaGetSymbolAddress((void**)&h, d_h);
    cudaGetSymbolAddress((void**)&wm, d_wm);
    cudaGetSymbolAddress((void**)&colh, d_colh);
    cudaGetSymbolAddress((void**)&coll, d_coll);
    cudaGetSymbolAddress((void**)&wbh, d_wbh);
    cudaGetSymbolAddress((void**)&wbl, d_wbl);

    cudaFuncSetAttribute(tc_gemm_kernel, cudaFuncAttributeMaxDynamicSharedMemorySize, GEMM_SMEM);

    auto SPLITW = [&](const float* w, int rows, int K, int Kp) {
        dim3 g((Kp + 255) / 256, rows);
        split_w_kernel<<<g, 256>>>(w, wbh, wbl, K, Kp);
    };
    auto GEMM = [&](const float* bias, float* C, int M, int N, int Kp, int act, int outPM) {
        dim3 grid((N + TBN - 1) / TBN, (M + TBM - 1) / TBM);
        tc_gemm_kernel<<<grid, 256, GEMM_SMEM>>>(colh, coll, wbh, wbl, bias, C, M, N, Kp, act, outPM);
    };

    // 1) assemble full-res image
    make_full_kernel<<<(10 * 192 * 192 + 255) / 256, 256>>>(input, full);

    // 2) feature network: 14 conv3x3 + lrelu at 192x192
    {
        dim3 g((128 + 255) / 256, 36864);
        im2col_split_k<3, 3><<<g, 256>>>(full, colh, coll, 10, 192, 192, 192, 1, 1, 90, 128);
    }
    SPLITW(fw0, 100, 90, 128);
    GEMM(fb0, f0, 36864, 100, 128, 1, 0);
    const float* fin = f0;
    float* fout = f1;
    for (int i = 0; i < 13; i++) {
        dim3 g((960 + 255) / 256, 36864);
        im2col_split_k<3, 3><<<g, 256>>>(fin, colh, coll, 100, 192, 192, 192, 1, 1, 900, 960);
        SPLITW(fw_rest + (size_t)i * 90000, 100, 900, 960);
        GEMM(fb_rest + i * 100, fout, 36864, 100, 960, 1, 0);
        const float* t = fin; fin = fout; fout = (float*)t;
    }

    // 3) weight network
    {
        dim3 g((1600 + 255) / 256, 2304);
        im2col_split_k<4, 4><<<g, 256>>>(fin, colh, coll, 100, 192, 192, 48, 4, 0, 1600, 1600);
    }
    SPLITW(ww0, 1024, 1600, 1600);
    GEMM(wb0, g0, 2304, 1024, 1600, 1, 0);
    const float* gin = g0;
    float* gout = g1;
    for (int i = 0; i < 3; i++) {
        dim3 g((9216 + 255) / 256, 2304);
        im2col_split_k<3, 3><<<g, 256>>>(gin, colh, coll, 1024, 48, 48, 48, 1, 1, 9216, 9216);
        SPLITW(ww_mid + (size_t)i * 9437184, 1024, 9216, 9216);
        GEMM(wb_mid + i * 1024, gout, 2304, 1024, 9216, 1, 0);
        const float* t = gin; gin = gout; gout = (float*)t;
    }
    {   // transpose+split g [1024][2304] -> col [2304][1024]
        dim3 g((2304 + 31) / 32, (1024 + 31) / 32);
        transpose_split_kernel<<<g, dim3(32, 8)>>>(gin, colh, coll, 1024, 2304);
    }
    SPLITW(ww1, 6272, 1024, 1024);
    GEMM(wb1, h, 2304, 6272, 1024, 1, 0);
    {   // transpose+split h [6272][2304] -> col [2304][6272]
        dim3 g((2304 + 31) / 32, (6272 + 31) / 32);
        transpose_split_kernel<<<g, dim3(32, 8)>>>(h, colh, coll, 6272, 2304);
    }
    SPLITW(ww2, 12544, 6272, 6272);
    GEMM(wb2, wm, 2304, 12544, 6272, 2, 1);   // tanh, PIXEL-major out

    // 4) per-pixel normal equations + solve + recombine
    solve_kernel<<<2304, 256>>>(wm, design, input, out);
}

// round 9
// speedup vs baseline: 2.7461x; 1.1118x over previous
#include <cuda_runtime.h>
#include <cuda_bf16.h>
#include <math.h>
#include <stdint.h>

// ---------------- scratch (static __device__, no runtime alloc) ----------------
__device__ __nv_bfloat16 d_inh[36864 * 64];     // input split, pixel-major [36864][64]
__device__ __nv_bfloat16 d_inl[36864 * 64];
__device__ __nv_bfloat16 d_fah[36864 * 128];    // feature ping [36864][128]
__device__ __nv_bfloat16 d_fal[36864 * 128];
__device__ __nv_bfloat16 d_fbh[36864 * 128];    // feature pong
__device__ __nv_bfloat16 d_fbl[36864 * 128];
__device__ __nv_bfloat16 d_gah[2304 * 1024];    // weight-net ping [2304][1024]
__device__ __nv_bfloat16 d_gal[2304 * 1024];
__device__ __nv_bfloat16 d_gbh[2304 * 1024];    // weight-net pong
__device__ __nv_bfloat16 d_gbl[2304 * 1024];
__device__ __nv_bfloat16 d_hh[2304 * 6272];     // half layer [2304][6272]
__device__ __nv_bfloat16 d_hl[2304 * 6272];
__device__ __nv_bfloat16 d_wbh[12544 * 6272];   // weight operand hi (max 78.7M)
__device__ __nv_bfloat16 d_wbl[12544 * 6272];   // weight operand lo
__device__ float d_wm[2304 * 12544];            // Wmap PIXEL-major [p][c]

// ---------------- helpers ----------------
__device__ __forceinline__ uint32_t smem_to_u32(const void* p) {
    uint32_t a;
    asm("{ .reg .u64 t; cvta.to.shared.u64 t, %1; cvt.u32.u64 %0, t; }" : "=r"(a) : "l"(p));
    return a;
}
__device__ __forceinline__ void ldsm4(uint32_t* r, uint32_t addr) {
    asm volatile("ldmatrix.sync.aligned.m8n8.x4.shared.b16 {%0,%1,%2,%3}, [%4];"
                 : "=r"(r[0]), "=r"(r[1]), "=r"(r[2]), "=r"(r[3]) : "r"(addr));
}
__device__ __forceinline__ void ldsm2(uint32_t* r, uint32_t addr) {
    asm volatile("ldmatrix.sync.aligned.m8n8.x2.shared.b16 {%0,%1}, [%2];"
                 : "=r"(r[0]), "=r"(r[1]) : "r"(addr));
}
__device__ __forceinline__ void mma_bf16(float* c, const uint32_t* a, const uint32_t* b) {
    asm volatile(
        "mma.sync.aligned.m16n8k16.row.col.f32.bf16.bf16.f32 "
        "{%0,%1,%2,%3}, {%4,%5,%6,%7}, {%8,%9}, {%0,%1,%2,%3};"
        : "+f"(c[0]), "+f"(c[1]), "+f"(c[2]), "+f"(c[3])
        : "r"(a[0]), "r"(a[1]), "r"(a[2]), "r"(a[3]), "r"(b[0]), "r"(b[1]));
}
__device__ __forceinline__ uint32_t swz(uint32_t base, int r, int c) {
    uint32_t off = (uint32_t)(r * 128 + c * 2);
    return base + (off ^ ((off >> 3) & 0x70));
}
__device__ __forceinline__ void cp16(uint32_t dst, const void* src, uint32_t sz) {
    asm volatile("cp.async.cg.shared.global [%0], [%1], 16, %2;"
                 :: "r"(dst), "l"(src), "r"(sz) : "memory");
}
__device__ __forceinline__ void split1(float v, __nv_bfloat16& hi, __nv_bfloat16& lo) {
    hi = __float2bfloat16(v);
    lo = __float2bfloat16(v - __bfloat162float(hi));
}

// ---------------- input split: (16,10,48,48) -> pixel-major [36864][64] hi/lo ------
__global__ void make_input_split(const float* __restrict__ in,
                                 __nv_bfloat16* __restrict__ oh, __nv_bfloat16* __restrict__ ol) {
    int idx = blockIdx.x * blockDim.x + threadIdx.x;
    if (idx >= 36864 * 64) return;
    int c = idx & 63;
    int m = idx >> 6;
    float v = 0.f;
    if (c < 10) {
        int x = m % 192, y = m / 192;
        int t = (y & 3) * 4 + (x & 3);
        v = in[((t * 10 + c) * 48 + (y >> 2)) * 48 + (x >> 2)];
    }
    __nv_bfloat16 hi, lo; split1(v, hi, lo);
    oh[idx] = hi; ol[idx] = lo;
}

// ---------------- weight reorg+split: w[Cout][Cin][KH][KW] -> [KH*KW][Cout][Kp] ----
__global__ void split_conv_w(const float* __restrict__ w,
                             __nv_bfloat16* __restrict__ oh, __nv_bfloat16* __restrict__ ol,
                             int Cout, int Cin, int KH, int KW, int Kp, int total) {
    int idx = blockIdx.x * blockDim.x + threadIdx.x;
    if (idx >= total) return;
    int k = idx % Kp;
    int n = (idx / Kp) % Cout;
    int off = idx / (Kp * Cout);
    int i = off / KW, j = off % KW;
    float v = (k < Cin) ? w[((n * Cin + k) * KH + i) * KW + j] : 0.f;
    __nv_bfloat16 hi, lo; split1(v, hi, lo);
    oh[idx] = hi; ol[idx] = lo;
}

// ---------------- 1x1 weight split: w[rows][K] -> [rows][K] (K already mult of 64) --
__global__ void split_w1x1(const float* __restrict__ w,
                           __nv_bfloat16* __restrict__ oh, __nv_bfloat16* __restrict__ ol,
                           int total) {
    int idx = blockIdx.x * blockDim.x + threadIdx.x;
    if (idx >= total) return;
    __nv_bfloat16 hi, lo; split1(w[idx], hi, lo);
    oh[idx] = hi; ol[idx] = lo;
}

// ---------------- implicit-conv bf16-split mma.sync GEMM ----------------
// out(m,n) = act( sum_off sum_k A[srcrow(m,off)][k] * B[off][n][k] + bias[n] )
// mode: 0 dense (noff=1), 1 = 3x3 pad1 shift conv on HxW grid (noff=9),
//       2 = 4x4 stride-4 (48x48 out of 192x192 in, noff=16)
// act: 1 lrelu(0.01), 2 tanh.  outSplit: 1 -> write bf16 hi/lo (zero-pad to Npad),
//                              0 -> write fp32 pixel-major stride Npad.
#define TBM 128
#define TBN 128
#define TKC 64
#define TILE_BYTES 16384
#define GEMM_SMEM (8 * TILE_BYTES)

__global__ __launch_bounds__(256, 1) void conv_gemm_kernel(
    const __nv_bfloat16* __restrict__ Ah, const __nv_bfloat16* __restrict__ Al,
    const __nv_bfloat16* __restrict__ Bh, const __nv_bfloat16* __restrict__ Bl,
    const float* __restrict__ bias,
    float* __restrict__ Cf, __nv_bfloat16* __restrict__ Coh, __nv_bfloat16* __restrict__ Col,
    int M, int N, int Npad, int Kp, int noff, int mode, int H, int W,
    int act, int outSplit) {
    extern __shared__ __align__(1024) char smem[];
    const uint32_t sb = smem_to_u32(smem);
    const int tid = threadIdx.x;
    const int wid = tid >> 5;
    const int lane = tid & 31;
    const int m0 = blockIdx.y * TBM, n0 = blockIdx.x * TBN;
    const int wm = (wid >> 2) * 64;
    const int wn = (wid & 3) * 32;

    const int row = tid >> 1;            // 0..127
    const int kq = (tid & 1) * 32;       // 0 / 32
    const int nkc = Kp / TKC;
    const int T = noff * nkc;

    // per-thread row geometry (loader role)
    const int am = m0 + row;
    const bool av = am < M;
    const int amc = av ? am : 0;
    const int ay = amc / W, ax = amc - (amc / W) * W;   // for mode 1
    const int sy = amc / 48, sx = amc - (amc / 48) * 48; // for mode 2
    const int bn = n0 + row;
    const bool bv = bn < N;
    const size_t brow = (size_t)(bv ? bn : (N - 1));
    const uint32_t bSz = bv ? 16u : 0u;

    float acc[4][4][4];
#pragma unroll
    for (int i = 0; i < 4; i++)
#pragma unroll
        for (int j = 0; j < 4; j++)
#pragma unroll
            for (int q = 0; q < 4; q++) acc[i][j][q] = 0.f;

    auto issueLoads = [&](int t) {
        const int off = t / nkc;
        const int kc = t - off * nkc;
        // A source row for this offset
        int srcrow;
        bool valid = av;
        if (mode == 1) {
            const int dy = off / 3 - 1, dx = off - (off / 3) * 3 - 1;
            const int yy = ay + dy, xx = ax + dx;
            valid = av && ((unsigned)yy < (unsigned)H) && ((unsigned)xx < (unsigned)W);
            srcrow = valid ? (yy * W + xx) : 0;
        } else if (mode == 2) {
            const int i = off >> 2, j = off & 3;
            srcrow = (4 * sy + i) * 192 + 4 * sx + j;
        } else {
            srcrow = amc;
        }
        const uint32_t aSz = valid ? 16u : 0u;
        const __nv_bfloat16* pAh = Ah + (size_t)srcrow * Kp + kc * TKC + kq;
        const __nv_bfloat16* pAl = Al + (size_t)srcrow * Kp + kc * TKC + kq;
        const __nv_bfloat16* pBh = Bh + ((size_t)off * N + brow) * Kp + kc * TKC + kq;
        const __nv_bfloat16* pBl = Bl + ((size_t)off * N + brow) * Kp + kc * TKC + kq;
        const int b = t & 1;
        const uint32_t tAh = sb + (b * 4 + 0) * TILE_BYTES;
        const uint32_t tAl = sb + (b * 4 + 1) * TILE_BYTES;
        const uint32_t tBh = sb + (b * 4 + 2) * TILE_BYTES;
        const uint32_t tBl = sb + (b * 4 + 3) * TILE_BYTES;
#pragma unroll
        for (int j = 0; j < 4; j++) {
            uint32_t d = swz(0, row, kq + j * 8);
            cp16(tAh + d, pAh + j * 8, aSz);
            cp16(tAl + d, pAl + j * 8, aSz);
            cp16(tBh + d, pBh + j * 8, bSz);
            cp16(tBl + d, pBl + j * 8, bSz);
        }
        asm volatile("cp.async.commit_group;" ::: "memory");
    };

    auto compute = [&](int b) {
        const uint32_t tAh = sb + (b * 4 + 0) * TILE_BYTES;
        const uint32_t tAl = sb + (b * 4 + 1) * TILE_BYTES;
        const uint32_t tBh = sb + (b * 4 + 2) * TILE_BYTES;
        const uint32_t tBl = sb + (b * 4 + 3) * TILE_BYTES;
        const int rA = wm + (lane & 15);
        const int cA = (lane >> 4) * 8;
        const int rB = wn + (lane & 7);
        const int cB = ((lane >> 3) & 1) * 8;
#pragma unroll
        for (int s = 0; s < 4; s++) {
            const int kk = s * 16;
            uint32_t aH[4][4], aL[4][4], bH[4][2], bL[4][2];
#pragma unroll
            for (int mt = 0; mt < 4; mt++) {
                ldsm4(aH[mt], swz(tAh, rA + mt * 16, kk + cA));
                ldsm4(aL[mt], swz(tAl, rA + mt * 16, kk + cA));
            }
#pragma unroll
            for (int nt = 0; nt < 4; nt++) {
                ldsm2(bH[nt], swz(tBh, rB + nt * 8, kk + cB));
                ldsm2(bL[nt], swz(tBl, rB + nt * 8, kk + cB));
            }
#pragma unroll
            for (int mt = 0; mt < 4; mt++)
#pragma unroll
                for (int nt = 0; nt < 4; nt++)
                    mma_bf16(acc[mt][nt], aH[mt], bH[nt]);
#pragma unroll
            for (int mt = 0; mt < 4; mt++)
#pragma unroll
                for (int nt = 0; nt < 4; nt++)
                    mma_bf16(acc[mt][nt], aH[mt], bL[nt]);
#pragma unroll
            for (int mt = 0; mt < 4; mt++)
#pragma unroll
                for (int nt = 0; nt < 4; nt++)
                    mma_bf16(acc[mt][nt], aL[mt], bH[nt]);
        }
    };

    // ---- pipeline ----
    issueLoads(0);
    for (int t = 0; t < T; t++) {
        if (t + 1 < T) {
            issueLoads(t + 1);
            asm volatile("cp.async.wait_group 1;" ::: "memory");
        } else {
            asm volatile("cp.async.wait_group 0;" ::: "memory");
        }
        __syncthreads();
        compute(t & 1);
        __syncthreads();
    }

    // ---- epilogue ----
    const int er = lane >> 2;
    const int ec = (lane & 3) * 2;
#pragma unroll
    for (int mt = 0; mt < 4; mt++) {
#pragma unroll
        for (int nt = 0; nt < 4; nt++) {
#pragma unroll
            for (int q = 0; q < 4; q++) {
                int m = m0 + wm + mt * 16 + er + (q >= 2 ? 8 : 0);
                int n = n0 + wn + nt * 8 + ec + (q & 1);
                if (m >= M || n >= Npad) continue;
                float v = 0.f;
                if (n < N) {
                    v = acc[mt][nt][q] + bias[n];
                    if (act == 1) v = v > 0.f ? v : 0.01f * v;
                    else if (act == 2) v = tanhf(v);
                }
                if (outSplit) {
                    __nv_bfloat16 hi, lo; split1(v, hi, lo);
                    Coh[(size_t)m * Npad + n] = hi;
                    Col[(size_t)m * Npad + n] = lo;
                } else if (n < N) {
                    Cf[(size_t)m * Npad + n] = v;
                }
            }
        }
    }
}

// ---------------- per-pixel normal-equations solve ----------------
__global__ __launch_bounds__(256) void solve_kernel(
    const float* __restrict__ wmap, const float* __restrict__ design,
    const float* __restrict__ input, float* __restrict__ out) {
    const int p = blockIdx.x;
    const int y = p / 48, x = p % 48;
    const int tid = threadIdx.x;
    __shared__ float sWm[16][17];
    __shared__ float sM[16][17];
    __shared__ float sX[16][8];
    __shared__ float sY[16][4];
    __shared__ float sXTW[7][16];
    __shared__ float sA[49];
    __shared__ float sB[21];
    __shared__ float sPara[7][3];

    if (tid < 49) sA[tid] = 0.f;
    if (tid < 21) sB[tid] = 0.f;
    const int t1 = tid >> 4, t2 = tid & 15;
    const float* wp = wmap + (size_t)p * 12544;

    for (int ni = 0; ni < 49; ni++) {
        int ny = y + ni / 7 - 3;
        int nx = x + ni % 7 - 3;
        bool inb = ((unsigned)ny < 48u) && ((unsigned)nx < 48u);
        __syncthreads();
        sWm[t1][t2] = wp[ni * 256 + tid];
        if (tid < 112) {
            int t = tid / 7, cd = tid - t * 7;
            sX[t][cd] = inb ? design[(t * 7 + cd) * 2304 + ny * 48 + nx] : 0.f;
        }
        if (tid >= 128 && tid < 176) {
            int r = tid - 128;
            int t = r / 3, ch = r - t * 3;
            sY[t][ch] = inb ? input[(t * 10 + ch) * 2304 + ny * 48 + nx] : 0.f;
        }
        __syncthreads();
        float s = (t1 == t2) ? 1.f : 0.f;
#pragma unroll
        for (int k = 0; k < 16; k++) s += sWm[t1][k] * sWm[t2][k];
        sM[t1][t2] = s;
        __syncthreads();
        if (tid < 112) {
            int cd = tid >> 4, t = tid & 15;
            float v = 0.f;
#pragma unroll
            for (int k = 0; k < 16; k++) v += sX[k][cd] * sM[k][t];
            sXTW[cd][t] = v;
        }
        __syncthreads();
        if (tid < 49) {
            int cd = tid / 7, ce = tid - cd * 7;
            float v = 0.f;
#pragma unroll
            for (int t = 0; t < 16; t++) v += sXTW[cd][t] * sX[t][ce];
            sA[tid] += v;
        }
        if (tid >= 64 && tid < 85) {
            int r = tid - 64;
            int cd = r / 3, ch = r - cd * 3;
            float v = 0.f;
#pragma unroll
            for (int t = 0; t < 16; t++) v += sXTW[cd][t] * sY[t][ch];
            sB[r] += v;
        }
    }
    __syncthreads();

    if (tid == 0) {
        float a[7][7], b[7][3];
        for (int i = 0; i < 7; i++) {
            for (int j = 0; j < 7; j++) a[i][j] = sA[i * 7 + j];
            a[i][i] += 0.01f;
            for (int c = 0; c < 3; c++) b[i][c] = sB[i * 3 + c];
        }
        for (int col = 0; col < 7; col++) {
            int piv = col;
            float mx = fabsf(a[col][col]);
            for (int r = col + 1; r < 7; r++) {
                float v = fabsf(a[r][col]);
                if (v > mx) { mx = v; piv = r; }
            }
            if (piv != col) {
                for (int c2 = 0; c2 < 7; c2++) { float t = a[col][c2]; a[col][c2] = a[piv][c2]; a[piv][c2] = t; }
                for (int c2 = 0; c2 < 3; c2++) { float t = b[col][c2]; b[col][c2] = b[piv][c2]; b[piv][c2] = t; }
            }
            float inv = 1.f / a[col][col];
            for (int r = 0; r < 7; r++) {
                if (r == col) continue;
                float f = a[r][col] * inv;
                for (int c2 = col; c2 < 7; c2++) a[r][c2] -= f * a[col][c2];
                for (int c2 = 0; c2 < 3; c2++) b[r][c2] -= f * b[col][c2];
            }
        }
        for (int i = 0; i < 7; i++)
            for (int c2 = 0; c2 < 3; c2++) sPara[i][c2] = b[i][c2] / a[i][i];
    }
    __syncthreads();

    if (tid < 48) {
        int t = tid / 3, ch = tid - t * 3;
        float s = 0.f;
#pragma unroll
        for (int cd = 0; cd < 7; cd++)
            s += design[(t * 7 + cd) * 2304 + y * 48 + x] * sPara[cd][ch];
        out[(t * 3 + ch) * 2304 + y * 48 + x] = s;
    }
}

// ---------------- launch ----------------
extern "C" void kernel_launch(void* const* d_in, const int* in_sizes, int n_in,
                              void* d_out, int out_size) {
    const float* input   = (const float*)d_in[0];
    const float* design  = (const float*)d_in[1];
    const float* fw0     = (const float*)d_in[2];
    const float* fb0     = (const float*)d_in[3];
    const float* fw_rest = (const float*)d_in[4];
    const float* fb_rest = (const float*)d_in[5];
    const float* ww0     = (const float*)d_in[6];
    const float* wb0     = (const float*)d_in[7];
    const float* ww_mid  = (const float*)d_in[8];
    const float* wb_mid  = (const float*)d_in[9];
    const float* ww1     = (const float*)d_in[10];
    const float* wb1     = (const float*)d_in[11];
    const float* ww2     = (const float*)d_in[12];
    const float* wb2     = (const float*)d_in[13];
    float* out = (float*)d_out;

    __nv_bfloat16 *inh, *inl, *fah, *fal, *fbh, *fbl, *gah, *gal, *gbh, *gbl, *hh, *hl, *wbh, *wbl;
    float* wm;
    cudaGetSymbolAddress((void**)&inh, d_inh);
    cudaGetSymbolAddress((void**)&inl, d_inl);
    cudaGetSymbolAddress((void**)&fah, d_fah);
    cudaGetSymbolAddress((void**)&fal, d_fal);
    cudaGetSymbolAddress((void**)&fbh, d_fbh);
    cudaGetSymbolAddress((void**)&fbl, d_fbl);
    cudaGetSymbolAddress((void**)&gah, d_gah);
    cudaGetSymbolAddress((void**)&gal, d_gal);
    cudaGetSymbolAddress((void**)&gbh, d_gbh);
    cudaGetSymbolAddress((void**)&gbl, d_gbl);
    cudaGetSymbolAddress((void**)&hh, d_hh);
    cudaGetSymbolAddress((void**)&hl, d_hl);
    cudaGetSymbolAddress((void**)&wbh, d_wbh);
    cudaGetSymbolAddress((void**)&wbl, d_wbl);
    cudaGetSymbolAddress((void**)&wm, d_wm);

    cudaFuncSetAttribute(conv_gemm_kernel, cudaFuncAttributeMaxDynamicSharedMemorySize, GEMM_SMEM);

    auto CONVGEMM = [&](const __nv_bfloat16* Ah, const __nv_bfloat16* Al,
                        const float* bias, float* Cf, __nv_bfloat16* Coh, __nv_bfloat16* Col,
                        int M, int N, int Npad, int Kp, int noff, int mode, int H, int W,
                        int act, int outSplit) {
        dim3 grid(Npad / TBN, (M + TBM - 1) / TBM);
        conv_gemm_kernel<<<grid, 256, GEMM_SMEM>>>(Ah, Al, wbh, wbl, bias, Cf, Coh, Col,
                                                   M, N, Npad, Kp, noff, mode, H, W, act, outSplit);
    };
    auto SPLITCW = [&](const float* w, int Cout, int Cin, int KH, int KW, int Kp) {
        int total = KH * KW * Cout * Kp;
        split_conv_w<<<(total + 255) / 256, 256>>>(w, wbh, wbl, Cout, Cin, KH, KW, Kp, total);
    };

    // 1) input -> split pixel-major [36864][64]
    make_input_split<<<(36864 * 64 + 255) / 256, 256>>>(input, inh, inl);

    // 2) feature network: 14x conv3x3 (implicit shifted GEMM at 192x192)
    SPLITCW(fw0, 100, 10, 3, 3, 64);
    CONVGEMM(inh, inl, fb0, nullptr, fah, fal, 36864, 100, 128, 64, 9, 1, 192, 192, 1, 1);
    const __nv_bfloat16 *cah = fah, *cal = fal;
    __nv_bfloat16 *nbh = fbh, *nbl = fbl;
    for (int i = 0; i < 13; i++) {
        SPLITCW(fw_rest + (size_t)i * 90000, 100, 100, 3, 3, 128);
        CONVGEMM(cah, cal, fb_rest + i * 100, nullptr, nbh, nbl,
                 36864, 100, 128, 128, 9, 1, 192, 192, 1, 1);
        const __nv_bfloat16* th = cah; const __nv_bfloat16* tl = cal;
        cah = nbh; cal = nbl; nbh = (__nv_bfloat16*)th; nbl = (__nv_bfloat16*)tl;
    }

    // 3) weight network
    SPLITCW(ww0, 1024, 100, 4, 4, 128);                 // 4x4 stride-4
    CONVGEMM(cah, cal, wb0, nullptr, gah, gal, 2304, 1024, 1024, 128, 16, 2, 48, 48, 1, 1);
    const __nv_bfloat16 *ggh = gah, *ggl = gal;
    __nv_bfloat16 *goh = gbh, *gol = gbl;
    for (int i = 0; i < 3; i++) {
        SPLITCW(ww_mid + (size_t)i * 9437184, 1024, 1024, 3, 3, 1024);
        CONVGEMM(ggh, ggl, wb_mid + i * 1024, nullptr, goh, gol,
                 2304, 1024, 1024, 1024, 9, 1, 48, 48, 1, 1);
        const __nv_bfloat16* th = ggh; const __nv_bfloat16* tl = ggl;
        ggh = goh; ggl = gol; goh = (__nv_bfloat16*)th; gol = (__nv_bfloat16*)tl;
    }
    {   // ww1 1x1: [6272][1024]
        int total = 6272 * 1024;
        split_w1x1<<<(total + 255) / 256, 256>>>(ww1, wbh, wbl, total);
    }
    CONVGEMM(ggh, ggl, wb1, nullptr, hh, hl, 2304, 6272, 6272, 1024, 1, 0, 48, 48, 1, 1);
    {   // ww2 1x1: [12544][6272]
        int total = 12544 * 6272;
        split_w1x1<<<(total + 255) / 256, 256>>>(ww2, wbh, wbl, total);
    }
    CONVGEMM(hh, hl, wb2, wm, nullptr, nullptr, 2304, 12544, 12544, 6272, 1, 0, 48, 48, 2, 0);

    // 4) per-pixel normal equations + solve + recombine
    solve_kernel<<<2304, 256>>>(wm, design, input, out);
}

// round 11
// speedup vs baseline: 2.7781x; 1.0117x over previous
#include <cuda_runtime.h>
#include <cuda_bf16.h>
#include <math.h>
#include <stdint.h>

// ---------------- scratch (static __device__, no runtime alloc) ----------------
__device__ __nv_bfloat16 d_inh[36864 * 64];     // input split, pixel-major [36864][64]
__device__ __nv_bfloat16 d_inl[36864 * 64];
__device__ __nv_bfloat16 d_fah[36864 * 128];    // feature ping [36864][128]
__device__ __nv_bfloat16 d_fal[36864 * 128];
__device__ __nv_bfloat16 d_fbh[36864 * 128];    // feature pong
__device__ __nv_bfloat16 d_fbl[36864 * 128];
__device__ __nv_bfloat16 d_gah[2304 * 1024];    // weight-net ping [2304][1024]
__device__ __nv_bfloat16 d_gal[2304 * 1024];
__device__ __nv_bfloat16 d_gbh[2304 * 1024];    // weight-net pong
__device__ __nv_bfloat16 d_gbl[2304 * 1024];
__device__ __nv_bfloat16 d_hh[2304 * 6272];     // half layer [2304][6272]
__device__ __nv_bfloat16 d_hl[2304 * 6272];
__device__ __nv_bfloat16 d_wbh[12544 * 6272];   // weight operand hi (max 78.7M)
__device__ __nv_bfloat16 d_wbl[12544 * 6272];   // weight operand lo
__device__ float d_wm[2304 * 12544];            // Wmap PIXEL-major [p][c]

// ---------------- helpers ----------------
__device__ __forceinline__ uint32_t smem_to_u32(const void* p) {
    uint32_t a;
    asm("{ .reg .u64 t; cvta.to.shared.u64 t, %1; cvt.u32.u64 %0, t; }" : "=r"(a) : "l"(p));
    return a;
}
__device__ __forceinline__ void ldsm4(uint32_t* r, uint32_t addr) {
    asm volatile("ldmatrix.sync.aligned.m8n8.x4.shared.b16 {%0,%1,%2,%3}, [%4];"
                 : "=r"(r[0]), "=r"(r[1]), "=r"(r[2]), "=r"(r[3]) : "r"(addr));
}
__device__ __forceinline__ void ldsm2(uint32_t* r, uint32_t addr) {
    asm volatile("ldmatrix.sync.aligned.m8n8.x2.shared.b16 {%0,%1}, [%2];"
                 : "=r"(r[0]), "=r"(r[1]) : "r"(addr));
}
__device__ __forceinline__ void mma_bf16(float* c, const uint32_t* a, const uint32_t* b) {
    asm volatile(
        "mma.sync.aligned.m16n8k16.row.col.f32.bf16.bf16.f32 "
        "{%0,%1,%2,%3}, {%4,%5,%6,%7}, {%8,%9}, {%0,%1,%2,%3};"
        : "+f"(c[0]), "+f"(c[1]), "+f"(c[2]), "+f"(c[3])
        : "r"(a[0]), "r"(a[1]), "r"(a[2]), "r"(a[3]), "r"(b[0]), "r"(b[1]));
}
__device__ __forceinline__ uint32_t swz(uint32_t base, int r, int c) {
    uint32_t off = (uint32_t)(r * 128 + c * 2);
    return base + (off ^ ((off >> 3) & 0x70));
}
__device__ __forceinline__ void cp16(uint32_t dst, const void* src, uint32_t sz) {
    asm volatile("cp.async.cg.shared.global [%0], [%1], 16, %2;"
                 :: "r"(dst), "l"(src), "r"(sz) : "memory");
}
__device__ __forceinline__ void split1(float v, __nv_bfloat16& hi, __nv_bfloat16& lo) {
    hi = __float2bfloat16(v);
    lo = __float2bfloat16(v - __bfloat162float(hi));
}

// ---------------- input split: (16,10,48,48) -> pixel-major [36864][64] hi/lo ------
__global__ void make_input_split(const float* __restrict__ in,
                                 __nv_bfloat16* __restrict__ oh, __nv_bfloat16* __restrict__ ol) {
    int idx = blockIdx.x * blockDim.x + threadIdx.x;
    if (idx >= 36864 * 64) return;
    int c = idx & 63;
    int m = idx >> 6;
    float v = 0.f;
    if (c < 10) {
        int x = m % 192, y = m / 192;
        int t = (y & 3) * 4 + (x & 3);
        v = in[((t * 10 + c) * 48 + (y >> 2)) * 48 + (x >> 2)];
    }
    __nv_bfloat16 hi, lo; split1(v, hi, lo);
    oh[idx] = hi; ol[idx] = lo;
}

// ---------------- weight reorg+split: w[Cout][Cin][KH][KW] -> [KH*KW][Cout][Kp] ----
__global__ void split_conv_w(const float* __restrict__ w,
                             __nv_bfloat16* __restrict__ oh, __nv_bfloat16* __restrict__ ol,
                             int Cout, int Cin, int KH, int KW, int Kp, int total) {
    int idx = blockIdx.x * blockDim.x + threadIdx.x;
    if (idx >= total) return;
    int k = idx % Kp;
    int n = (idx / Kp) % Cout;
    int off = idx / (Kp * Cout);
    int i = off / KW, j = off % KW;
    float v = (k < Cin) ? w[((n * Cin + k) * KH + i) * KW + j] : 0.f;
    __nv_bfloat16 hi, lo; split1(v, hi, lo);
    oh[idx] = hi; ol[idx] = lo;
}

// ---------------- 1x1 weight split ----------------
__global__ void split_w1x1(const float* __restrict__ w,
                           __nv_bfloat16* __restrict__ oh, __nv_bfloat16* __restrict__ ol,
                           int total) {
    int idx = blockIdx.x * blockDim.x + threadIdx.x;
    if (idx >= total) return;
    __nv_bfloat16 hi, lo; split1(w[idx], hi, lo);
    oh[idx] = hi; ol[idx] = lo;
}

// ---------------- implicit-conv bf16-split mma.sync GEMM (3-stage pipeline) --------
// out(m,n) = act( sum_off sum_k A[srcrow(m,off)][k] * B[off][n][k] + bias[n] )
// mode: 0 dense, 1 = 3x3 pad1 shift conv, 2 = 4x4 stride-4 (192->48).
// 1D grid with N-panel (8) rasterization for L2 locality.
#define TBM 128
#define TBN 128
#define TKC 64
#define TILE_BYTES 16384
#define NSTAGE 3
#define GEMM_SMEM (NSTAGE * 4 * TILE_BYTES)   // 196608

__global__ __launch_bounds__(256, 1) void conv_gemm_kernel(
    const __nv_bfloat16* __restrict__ Ah, const __nv_bfloat16* __restrict__ Al,
    const __nv_bfloat16* __restrict__ Bh, const __nv_bfloat16* __restrict__ Bl,
    const float* __restrict__ bias,
    float* __restrict__ Cf, __nv_bfloat16* __restrict__ Coh, __nv_bfloat16* __restrict__ Col,
    int M, int N, int Npad, int Kp, int noff, int mode, int H, int W,
    int act, int outSplit, int Mb, int Nb) {
    extern __shared__ __align__(1024) char smem[];
    const uint32_t sb = smem_to_u32(smem);
    const int tid = threadIdx.x;
    const int wid = tid >> 5;
    const int lane = tid & 31;

    // ---- panel-swizzled rasterization: panels of 8 N-blocks x all M-blocks ----
    int mb, nb;
    {
        const int id = blockIdx.x;
        const int fullPanels = Nb >> 3;
        const int fullCTAs = fullPanels * 8 * Mb;
        if (id < fullCTAs) {
            const int panel = id / (8 * Mb);
            const int rem = id - panel * (8 * Mb);
            mb = rem % Mb;
            nb = panel * 8 + rem / Mb;
        } else {
            const int r = id - fullCTAs;
            mb = r % Mb;
            nb = fullPanels * 8 + r / Mb;
        }
    }
    const int m0 = mb * TBM, n0 = nb * TBN;
    const int wm = (wid >> 2) * 64;
    const int wn = (wid & 3) * 32;

    const int row = tid >> 1;            // 0..127
    const int kq = (tid & 1) * 32;       // 0 / 32
    const int nkc = Kp / TKC;
    const int T = noff * nkc;

    // per-thread row geometry (loader role)
    const int am = m0 + row;
    const bool av = am < M;
    const int amc = av ? am : 0;
    const int ay = amc / W, ax = amc - (amc / W) * W;    // mode 1
    const int sy = amc / 48, sx = amc - (amc / 48) * 48; // mode 2
    const int bn = n0 + row;
    const bool bv = bn < N;
    const size_t brow = (size_t)(bv ? bn : (N - 1));
    const uint32_t bSz = bv ? 16u : 0u;

    float acc[4][4][4];
#pragma unroll
    for (int i = 0; i < 4; i++)
#pragma unroll
        for (int j = 0; j < 4; j++)
#pragma unroll
            for (int q = 0; q < 4; q++) acc[i][j][q] = 0.f;

    auto issueLoads = [&](int t) {
        const int off = t / nkc;
        const int kc = t - off * nkc;
        int srcrow;
        bool valid = av;
        if (mode == 1) {
            const int dy = off / 3 - 1, dx = off - (off / 3) * 3 - 1;
            const int yy = ay + dy, xx = ax + dx;
            valid = av && ((unsigned)yy < (unsigned)H) && ((unsigned)xx < (unsigned)W);
            srcrow = valid ? (yy * W + xx) : 0;
        } else if (mode == 2) {
            const int i = off >> 2, j = off & 3;
            srcrow = (4 * sy + i) * 192 + 4 * sx + j;
        } else {
            srcrow = amc;
        }
        const uint32_t aSz = valid ? 16u : 0u;
        const __nv_bfloat16* pAh = Ah + (size_t)srcrow * Kp + kc * TKC + kq;
        const __nv_bfloat16* pAl = Al + (size_t)srcrow * Kp + kc * TKC + kq;
        const __nv_bfloat16* pBh = Bh + ((size_t)off * N + brow) * Kp + kc * TKC + kq;
        const __nv_bfloat16* pBl = Bl + ((size_t)off * N + brow) * Kp + kc * TKC + kq;
        const int b = t % NSTAGE;
        const uint32_t tAh = sb + (b * 4 + 0) * TILE_BYTES;
        const uint32_t tAl = sb + (b * 4 + 1) * TILE_BYTES;
        const uint32_t tBh = sb + (b * 4 + 2) * TILE_BYTES;
        const uint32_t tBl = sb + (b * 4 + 3) * TILE_BYTES;
#pragma unroll
        for (int j = 0; j < 4; j++) {
            uint32_t d = swz(0, row, kq + j * 8);
            cp16(tAh + d, pAh + j * 8, aSz);
            cp16(tAl + d, pAl + j * 8, aSz);
            cp16(tBh + d, pBh + j * 8, bSz);
            cp16(tBl + d, pBl + j * 8, bSz);
        }
        asm volatile("cp.async.commit_group;" ::: "memory");
    };

    auto compute = [&](int b) {
        const uint32_t tAh = sb + (b * 4 + 0) * TILE_BYTES;
        const uint32_t tAl = sb + (b * 4 + 1) * TILE_BYTES;
        const uint32_t tBh = sb + (b * 4 + 2) * TILE_BYTES;
        const uint32_t tBl = sb + (b * 4 + 3) * TILE_BYTES;
        const int rA = wm + (lane & 15);
        const int cA = (lane >> 4) * 8;
        const int rB = wn + (lane & 7);
        const int cB = ((lane >> 3) & 1) * 8;
#pragma unroll
        for (int s = 0; s < 4; s++) {
            const int kk = s * 16;
            uint32_t aH[4][4], aL[4][4], bH[4][2], bL[4][2];
#pragma unroll
            for (int mt = 0; mt < 4; mt++) {
                ldsm4(aH[mt], swz(tAh, rA + mt * 16, kk + cA));
                ldsm4(aL[mt], swz(tAl, rA + mt * 16, kk + cA));
            }
#pragma unroll
            for (int nt = 0; nt < 4; nt++) {
                ldsm2(bH[nt], swz(tBh, rB + nt * 8, kk + cB));
                ldsm2(bL[nt], swz(tBl, rB + nt * 8, kk + cB));
            }
#pragma unroll
            for (int mt = 0; mt < 4; mt++)
#pragma unroll
                for (int nt = 0; nt < 4; nt++)
                    mma_bf16(acc[mt][nt], aH[mt], bH[nt]);
#pragma unroll
            for (int mt = 0; mt < 4; mt++)
#pragma unroll
                for (int nt = 0; nt < 4; nt++)
                    mma_bf16(acc[mt][nt], aH[mt], bL[nt]);
#pragma unroll
            for (int mt = 0; mt < 4; mt++)
#pragma unroll
                for (int nt = 0; nt < 4; nt++)
                    mma_bf16(acc[mt][nt], aL[mt], bH[nt]);
        }
    };

    // ---- 3-stage pipeline, one barrier per chunk ----
    issueLoads(0);
    if (T > 1) issueLoads(1);
    for (int t = 0; t < T; t++) {
        if (t + 1 < T) {
            asm volatile("cp.async.wait_group 1;" ::: "memory");
        } else {
            asm volatile("cp.async.wait_group 0;" ::: "memory");
        }
        __syncthreads();   // chunk t visible to all; compute(t-1) finished by all
        if (t + 2 < T) issueLoads(t + 2);   // writes buf (t+2)%3 == (t-1)%3: safe after barrier
        compute(t % NSTAGE);
    }

    // ---- epilogue ----
    const int er = lane >> 2;
    const int ec = (lane & 3) * 2;
#pragma unroll
    for (int mt = 0; mt < 4; mt++) {
#pragma unroll
        for (int nt = 0; nt < 4; nt++) {
#pragma unroll
            for (int q = 0; q < 4; q++) {
                int m = m0 + wm + mt * 16 + er + (q >= 2 ? 8 : 0);
                int n = n0 + wn + nt * 8 + ec + (q & 1);
                if (m >= M || n >= Npad) continue;
                float v = 0.f;
                if (n < N) {
                    v = acc[mt][nt][q] + bias[n];
                    if (act == 1) v = v > 0.f ? v : 0.01f * v;
                    else if (act == 2) v = tanhf(v);
                }
                if (outSplit) {
                    __nv_bfloat16 hi, lo; split1(v, hi, lo);
                    Coh[(size_t)m * Npad + n] = hi;
                    Col[(size_t)m * Npad + n] = lo;
                } else if (n < N) {
                    Cf[(size_t)m * Npad + n] = v;
                }
            }
        }
    }
}

// ---------------- per-pixel normal-equations solve ----------------
__global__ __launch_bounds__(256) void solve_kernel(
    const float* __restrict__ wmap, const float* __restrict__ design,
    const float* __restrict__ input, float* __restrict__ out) {
    const int p = blockIdx.x;
    const int y = p / 48, x = p % 48;
    const int tid = threadIdx.x;
    __shared__ float sWm[16][17];
    __shared__ float sM[16][17];
    __shared__ float sX[16][8];
    __shared__ float sY[16][4];
    __shared__ float sXTW[7][16];
    __shared__ float sA[49];
    __shared__ float sB[21];
    __shared__ float sPara[7][3];

    if (tid < 49) sA[tid] = 0.f;
    if (tid < 21) sB[tid] = 0.f;
    const int t1 = tid >> 4, t2 = tid & 15;
    const float* wp = wmap + (size_t)p * 12544;

    for (int ni = 0; ni < 49; ni++) {
        int ny = y + ni / 7 - 3;
        int nx = x + ni % 7 - 3;
        bool inb = ((unsigned)ny < 48u) && ((unsigned)nx < 48u);
        __syncthreads();
        sWm[t1][t2] = wp[ni * 256 + tid];
        if (tid < 112) {
            int t = tid / 7, cd = tid - t * 7;
            sX[t][cd] = inb ? design[(t * 7 + cd) * 2304 + ny * 48 + nx] : 0.f;
        }
        if (tid >= 128 && tid < 176) {
            int r = tid - 128;
            int t = r / 3, ch = r - t * 3;
            sY[t][ch] = inb ? input[(t * 10 + ch) * 2304 + ny * 48 + nx] : 0.f;
        }
        __syncthreads();
        float s = (t1 == t2) ? 1.f : 0.f;
#pragma unroll
        for (int k = 0; k < 16; k++) s += sWm[t1][k] * sWm[t2][k];
        sM[t1][t2] = s;
        __syncthreads();
        if (tid < 112) {
            int cd = tid >> 4, t = tid & 15;
            float v = 0.f;
#pragma unroll
            for (int k = 0; k < 16; k++) v += sX[k][cd] * sM[k][t];
            sXTW[cd][t] = v;
        }
        __syncthreads();
        if (tid < 49) {
            int cd = tid / 7, ce = tid - cd * 7;
            float v = 0.f;
#pragma unroll
            for (int t = 0; t < 16; t++) v += sXTW[cd][t] * sX[t][ce];
            sA[tid] += v;
        }
        if (tid >= 64 && tid < 85) {
            int r = tid - 64;
            int cd = r / 3, ch = r - cd * 3;
            float v = 0.f;
#pragma unroll
            for (int t = 0; t < 16; t++) v += sXTW[cd][t] * sY[t][ch];
            sB[r] += v;
        }
    }
    __syncthreads();

    if (tid == 0) {
        float a[7][7], b[7][3];
        for (int i = 0; i < 7; i++) {
            for (int j = 0; j < 7; j++) a[i][j] = sA[i * 7 + j];
            a[i][i] += 0.01f;
            for (int c = 0; c < 3; c++) b[i][c] = sB[i * 3 + c];
        }
        for (int col = 0; col < 7; col++) {
            int piv = col;
            float mx = fabsf(a[col][col]);
            for (int r = col + 1; r < 7; r++) {
                float v = fabsf(a[r][col]);
                if (v > mx) { mx = v; piv = r; }
            }
            if (piv != col) {
                for (int c2 = 0; c2 < 7; c2++) { float t = a[col][c2]; a[col][c2] = a[piv][c2]; a[piv][c2] = t; }
                for (int c2 = 0; c2 < 3; c2++) { float t = b[col][c2]; b[col][c2] = b[piv][c2]; b[piv][c2] = t; }
            }
            float inv = 1.f / a[col][col];
            for (int r = 0; r < 7; r++) {
                if (r == col) continue;
                float f = a[r][col] * inv;
                for (int c2 = col; c2 < 7; c2++) a[r][c2] -= f * a[col][c2];
                for (int c2 = 0; c2 < 3; c2++) b[r][c2] -= f * b[col][c2];
            }
        }
        for (int i = 0; i < 7; i++)
            for (int c2 = 0; c2 < 3; c2++) sPara[i][c2] = b[i][c2] / a[i][i];
    }
    __syncthreads();

    if (tid < 48) {
        int t = tid / 3, ch = tid - t * 3;
        float s = 0.f;
#pragma unroll
        for (int cd = 0; cd < 7; cd++)
            s += design[(t * 7 + cd) * 2304 + y * 48 + x] * sPara[cd][ch];
        out[(t * 3 + ch) * 2304 + y * 48 + x] = s;
    }
}

// ---------------- launch ----------------
extern "C" void kernel_launch(void* const* d_in, const int* in_sizes, int n_in,
                              void* d_out, int out_size) {
    const float* input   = (const float*)d_in[0];
    const float* design  = (const float*)d_in[1];
    const float* fw0     = (const float*)d_in[2];
    const float* fb0     = (const float*)d_in[3];
    const float* fw_rest = (const float*)d_in[4];
    const float* fb_rest = (const float*)d_in[5];
    const float* ww0     = (const float*)d_in[6];
    const float* wb0     = (const float*)d_in[7];
    const float* ww_mid  = (const float*)d_in[8];
    const float* wb_mid  = (const float*)d_in[9];
    const float* ww1     = (const float*)d_in[10];
    const float* wb1     = (const float*)d_in[11];
    const float* ww2     = (const float*)d_in[12];
    const float* wb2     = (const float*)d_in[13];
    float* out = (float*)d_out;

    __nv_bfloat16 *inh, *inl, *fah, *fal, *fbh, *fbl, *gah, *gal, *gbh, *gbl, *hh, *hl, *wbh, *wbl;
    float* wm;
    cudaGetSymbolAddress((void**)&inh, d_inh);
    cudaGetSymbolAddress((void**)&inl, d_inl);
    cudaGetSymbolAddress((void**)&fah, d_fah);
    cudaGetSymbolAddress((void**)&fal, d_fal);
    cudaGetSymbolAddress((void**)&fbh, d_fbh);
    cudaGetSymbolAddress((void**)&fbl, d_fbl);
    cudaGetSymbolAddress((void**)&gah, d_gah);
    cudaGetSymbolAddress((void**)&gal, d_gal);
    cudaGetSymbolAddress((void**)&gbh, d_gbh);
    cudaGetSymbolAddress((void**)&gbl, d_gbl);
    cudaGetSymbolAddress((void**)&hh, d_hh);
    cudaGetSymbolAddress((void**)&hl, d_hl);
    cudaGetSymbolAddress((void**)&wbh, d_wbh);
    cudaGetSymbolAddress((void**)&wbl, d_wbl);
    cudaGetSymbolAddress((void**)&wm, d_wm);

    cudaFuncSetAttribute(conv_gemm_kernel, cudaFuncAttributeMaxDynamicSharedMemorySize, GEMM_SMEM);

    auto CONVGEMM = [&](const __nv_bfloat16* Ah, const __nv_bfloat16* Al,
                        const float* bias, float* Cf, __nv_bfloat16* Coh, __nv_bfloat16* Col,
                        int M, int N, int Npad, int Kp, int noff, int mode, int H, int W,
                        int act, int outSplit) {
        int Mb = (M + TBM - 1) / TBM;
        int Nb = Npad / TBN;
        conv_gemm_kernel<<<Mb * Nb, 256, GEMM_SMEM>>>(Ah, Al, wbh, wbl, bias, Cf, Coh, Col,
                                                      M, N, Npad, Kp, noff, mode, H, W,
                                                      act, outSplit, Mb, Nb);
    };
    auto SPLITCW = [&](const float* w, int Cout, int Cin, int KH, int KW, int Kp) {
        int total = KH * KW * Cout * Kp;
        split_conv_w<<<(total + 255) / 256, 256>>>(w, wbh, wbl, Cout, Cin, KH, KW, Kp, total);
    };

    // 1) input -> split pixel-major [36864][64]
    make_input_split<<<(36864 * 64 + 255) / 256, 256>>>(input, inh, inl);

    // 2) feature network: 14x conv3x3 (implicit shifted GEMM at 192x192)
    SPLITCW(fw0, 100, 10, 3, 3, 64);
    CONVGEMM(inh, inl, fb0, nullptr, fah, fal, 36864, 100, 128, 64, 9, 1, 192, 192, 1, 1);
    const __nv_bfloat16 *cah = fah, *cal = fal;
    __nv_bfloat16 *nbh = fbh, *nbl = fbl;
    for (int i = 0; i < 13; i++) {
        SPLITCW(fw_rest + (size_t)i * 90000, 100, 100, 3, 3, 128);
        CONVGEMM(cah, cal, fb_rest + i * 100, nullptr, nbh, nbl,
                 36864, 100, 128, 128, 9, 1, 192, 192, 1, 1);
        const __nv_bfloat16* th = cah; const __nv_bfloat16* tl = cal;
        cah = nbh; cal = nbl; nbh = (__nv_bfloat16*)th; nbl = (__nv_bfloat16*)tl;
    }

    // 3) weight network
    SPLITCW(ww0, 1024, 100, 4, 4, 128);                 // 4x4 stride-4
    CONVGEMM(cah, cal, wb0, nullptr, gah, gal, 2304, 1024, 1024, 128, 16, 2, 48, 48, 1, 1);
    const __nv_bfloat16 *ggh = gah, *ggl = gal;
    __nv_bfloat16 *goh = gbh, *gol = gbl;
    for (int i = 0; i < 3; i++) {
        SPLITCW(ww_mid + (size_t)i * 9437184, 1024, 1024, 3, 3, 1024);
        CONVGEMM(ggh, ggl, wb_mid + i * 1024, nullptr, goh, gol,
                 2304, 1024, 1024, 1024, 9, 1, 48, 48, 1, 1);
        const __nv_bfloat16* th = ggh; const __nv_bfloat16* tl = ggl;
        ggh = goh; ggl = gol; goh = (__nv_bfloat16*)th; gol = (__nv_bfloat16*)tl;
    }
    {   // ww1 1x1: [6272][1024]
        int total = 6272 * 1024;
        split_w1x1<<<(total + 255) / 256, 256>>>(ww1, wbh, wbl, total);
    }
    CONVGEMM(ggh, ggl, wb1, nullptr, hh, hl, 2304, 6272, 6272, 1024, 1, 0, 48, 48, 1, 1);
    {   // ww2 1x1: [12544][6272]
        int total = 12544 * 6272;
        split_w1x1<<<(total + 255) / 256, 256>>>(ww2, wbh, wbl, total);
    }
    CONVGEMM(hh, hl, wb2, wm, nullptr, nullptr, 2304, 12544, 12544, 6272, 1, 0, 48, 48, 2, 0);

    // 4) per-pixel normal equations + solve + recombine
    solve_kernel<<<2304, 256>>>(wm, design, input, out);
}